// round 1
// baseline (speedup 1.0000x reference)
#include <cuda_runtime.h>
#include <cuda_bf16.h>

// Problem constants
#define Bsz 2
#define SEQ 2048
#define EMB 2048
#define NH  32
#define NKV 8
#define HD  64
#define GRP 4          // NH / NKV
#define BSxS (Bsz*SEQ) // 4096

// ---------------- scratch (static device globals; no allocs allowed) --------
__device__ float g_q[(size_t)BSxS * EMB];      // x@Wq, roped+scaled in place, layout (B,S,H,D)
__device__ float g_k[(size_t)BSxS * NKV * HD]; // x@Wk raw, layout (B,S,KV,D)
__device__ float g_v[(size_t)BSxS * NKV * HD]; // x@Wv raw
__device__ float g_attn[(size_t)BSxS * EMB];   // attention output (B,S,H,D)=(B,S,E)

// ---------------- SGEMM: C[M,N] = A[M,K] @ B[K,N], row-major ----------------
#define GBM 128
#define GBN 128
#define GBK 16
// 256 threads, each computes 8x8
__global__ __launch_bounds__(256) void sgemm_kernel(
    const float* __restrict__ A, const float* __restrict__ B,
    float* __restrict__ C, int M, int N, int K)
{
    __shared__ float As[GBK][GBM + 4];
    __shared__ float Bs[GBK][GBN];

    int tid = threadIdx.x;
    int bx = blockIdx.x;   // N tile
    int by = blockIdx.y;   // M tile
    int tx = tid & 15;     // 0..15
    int ty = tid >> 4;     // 0..15

    const float* Ab = A + (size_t)by * GBM * K;
    const float* Bb = B + (size_t)bx * GBN;

    float acc[8][8];
#pragma unroll
    for (int i = 0; i < 8; i++)
#pragma unroll
        for (int j = 0; j < 8; j++) acc[i][j] = 0.f;

    for (int k0 = 0; k0 < K; k0 += GBK) {
        // Load A tile (GBM x GBK) -> As transposed [k][m]
#pragma unroll
        for (int i = 0; i < 2; i++) {
            int f = tid + i * 256;            // float4 index, 512 total
            int row = f >> 2;                 // 4 float4 per row (16 floats)
            int col = (f & 3) << 2;
            float4 a = *(const float4*)(Ab + (size_t)row * K + k0 + col);
            As[col + 0][row] = a.x;
            As[col + 1][row] = a.y;
            As[col + 2][row] = a.z;
            As[col + 3][row] = a.w;
        }
        // Load B tile (GBK x GBN) -> Bs direct
#pragma unroll
        for (int i = 0; i < 2; i++) {
            int f = tid + i * 256;
            int row = f >> 5;                 // 32 float4 per row (128 floats)
            int col = (f & 31) << 2;
            *(float4*)&Bs[row][col] = *(const float4*)(Bb + (size_t)(k0 + row) * N + col);
        }
        __syncthreads();

#pragma unroll
        for (int kk = 0; kk < GBK; kk++) {
            float ra[8], rb[8];
            *(float4*)&ra[0] = *(const float4*)&As[kk][ty * 8];
            *(float4*)&ra[4] = *(const float4*)&As[kk][ty * 8 + 4];
            *(float4*)&rb[0] = *(const float4*)&Bs[kk][tx * 8];
            *(float4*)&rb[4] = *(const float4*)&Bs[kk][tx * 8 + 4];
#pragma unroll
            for (int i = 0; i < 8; i++)
#pragma unroll
                for (int j = 0; j < 8; j++)
                    acc[i][j] += ra[i] * rb[j];
        }
        __syncthreads();
    }

    int crow = by * GBM + ty * 8;
    int ccol = bx * GBN + tx * 8;
#pragma unroll
    for (int i = 0; i < 8; i++) {
        *(float4*)&C[(size_t)(crow + i) * N + ccol]     = *(float4*)&acc[i][0];
        *(float4*)&C[(size_t)(crow + i) * N + ccol + 4] = *(float4*)&acc[i][4];
    }
}

// ---------------- RoPE on Q (in place, fold in 1/sqrt(HD) scale) ------------
__global__ void rope_q_kernel(float* __restrict__ q,
                              const float* __restrict__ cosp,
                              const float* __restrict__ sinp)
{
    int idx = blockIdx.x * blockDim.x + threadIdx.x;   // B*S*H*32 = 4194304
    if (idx >= Bsz * SEQ * NH * 32) return;
    int d  = idx & 31;
    int h  = (idx >> 5) & 31;
    int bs = idx >> 10;          // b*S+s
    int s  = bs & (SEQ - 1);
    float* base = q + ((size_t)bs * NH + h) * HD;
    float x1 = base[d];
    float x2 = base[d + 32];
    float c  = cosp[s * HD + d];
    float sn = sinp[s * HD + d];
    const float scale = 0.125f;  // 1/sqrt(64)
    base[d]      = (x1 * c - x2 * sn) * scale;
    base[d + 32] = (x2 * c + x1 * sn) * scale;
}

// ---------------- RoPE on K + transpose (B,S,KV,D)->(B,KV,S,D) -------------
__global__ void rope_k_kernel(const float* __restrict__ kraw,
                              const float* __restrict__ cosp,
                              const float* __restrict__ sinp,
                              float* __restrict__ nk)
{
    int idx = blockIdx.x * blockDim.x + threadIdx.x;   // B*S*KV*32 = 1048576
    if (idx >= Bsz * SEQ * NKV * 32) return;
    int d  = idx & 31;
    int kv = (idx >> 5) & 7;
    int bs = idx >> 8;           // b*S+s
    int s  = bs & (SEQ - 1);
    int b  = bs >> 11;
    const float* src = kraw + (size_t)bs * (NKV * HD) + kv * HD;
    float x1 = src[d];
    float x2 = src[d + 32];
    float c  = cosp[s * HD + d];
    float sn = sinp[s * HD + d];
    float* dst = nk + (((size_t)b * NKV + kv) * SEQ + s) * HD;
    dst[d]      = x1 * c - x2 * sn;
    dst[d + 32] = x2 * c + x1 * sn;
}

// ---------------- V transpose (B,S,KV,D)->(B,KV,S,D) ------------------------
__global__ void vtrans_kernel(const float* __restrict__ vraw, float* __restrict__ nv)
{
    int idx = blockIdx.x * blockDim.x + threadIdx.x;   // B*S*KV*D = 2097152
    if (idx >= Bsz * SEQ * NKV * HD) return;
    int d  = idx & 63;
    int kv = (idx >> 6) & 7;
    int bs = idx >> 9;
    int s  = bs & (SEQ - 1);
    int b  = bs >> 11;
    nv[(((size_t)b * NKV + kv) * SEQ + s) * HD + d] = vraw[(size_t)bs * (NKV * HD) + kv * HD + d];
}

// ---------------- Flash attention (causal), row-per-thread ------------------
// grid: (S/64, NH, B), block 64 threads. Q already scaled by 1/8.
__global__ __launch_bounds__(64) void attn_kernel(
    const float* __restrict__ q,    // (B,S,H,D)
    const float* __restrict__ kk,   // (B,KV,S,D)
    const float* __restrict__ vv,   // (B,KV,S,D)
    float* __restrict__ out)        // (B,S,H,D)
{
    int qt  = blockIdx.x;
    int h   = blockIdx.y;
    int b   = blockIdx.z;
    int kv  = h >> 2;               // GROUP=4
    int tid = threadIdx.x;
    int s0  = qt * 64 + tid;

    __shared__ float Ks[64][68];
    __shared__ float Vs[64][68];

    float qreg[HD];
    const float* qp = q + (((size_t)b * SEQ + s0) * NH + h) * HD;
#pragma unroll
    for (int i = 0; i < 16; i++) {
        float4 t = ((const float4*)qp)[i];
        qreg[4 * i]     = t.x;
        qreg[4 * i + 1] = t.y;
        qreg[4 * i + 2] = t.z;
        qreg[4 * i + 3] = t.w;
    }
    float o[HD];
#pragma unroll
    for (int i = 0; i < HD; i++) o[i] = 0.f;
    float m = -1e30f, l = 0.f;

    const float* kbase = kk + ((size_t)b * NKV + kv) * SEQ * HD;
    const float* vbase = vv + ((size_t)b * NKV + kv) * SEQ * HD;

    for (int kt = 0; kt <= qt; kt++) {
        __syncthreads();
        const float4* ksrc = (const float4*)(kbase + (size_t)kt * 64 * HD);
        const float4* vsrc = (const float4*)(vbase + (size_t)kt * 64 * HD);
#pragma unroll
        for (int i = 0; i < 16; i++) {
            int f   = i * 64 + tid;       // float4 index, 1024 total
            int row = f >> 4;             // 16 float4 per row
            int col = (f & 15) << 2;
            *(float4*)&Ks[row][col] = ksrc[f];
            *(float4*)&Vs[row][col] = vsrc[f];
        }
        __syncthreads();

        int jmax = (kt < qt) ? 64 : (tid + 1);
        for (int j = 0; j < jmax; j++) {
            float s = 0.f;
#pragma unroll
            for (int i = 0; i < 16; i++) {
                float4 kr = *(const float4*)&Ks[j][i * 4];
                s += qreg[4 * i] * kr.x + qreg[4 * i + 1] * kr.y +
                     qreg[4 * i + 2] * kr.z + qreg[4 * i + 3] * kr.w;
            }
            float mnew = fmaxf(m, s);
            float corr = __expf(m - mnew);
            float p    = __expf(s - mnew);
            l = l * corr + p;
            m = mnew;
#pragma unroll
            for (int i = 0; i < 16; i++) {
                float4 vr = *(const float4*)&Vs[j][i * 4];
                o[4 * i]     = o[4 * i]     * corr + p * vr.x;
                o[4 * i + 1] = o[4 * i + 1] * corr + p * vr.y;
                o[4 * i + 2] = o[4 * i + 2] * corr + p * vr.z;
                o[4 * i + 3] = o[4 * i + 3] * corr + p * vr.w;
            }
        }
    }

    float inv = 1.f / l;
    float* op = out + (((size_t)b * SEQ + s0) * NH + h) * HD;
#pragma unroll
    for (int i = 0; i < 16; i++) {
        float4 t;
        t.x = o[4 * i] * inv;
        t.y = o[4 * i + 1] * inv;
        t.z = o[4 * i + 2] * inv;
        t.w = o[4 * i + 3] * inv;
        ((float4*)op)[i] = t;
    }
}

// ---------------- launch -----------------------------------------------------
extern "C" void kernel_launch(void* const* d_in, const int* in_sizes, int n_in,
                              void* d_out, int out_size)
{
    const float* x    = (const float*)d_in[0];
    // d_in[1] = mask (causal triu k=1) — implemented analytically
    const float* cosp = (const float*)d_in[2];
    const float* sinp = (const float*)d_in[3];
    const float* Wq   = (const float*)d_in[4];
    const float* Wk   = (const float*)d_in[5];
    const float* Wv   = (const float*)d_in[6];
    const float* Wo   = (const float*)d_in[7];

    float* out    = (float*)d_out;
    float* next_k = out + (size_t)Bsz * SEQ * EMB;                 // (B,KV,S,D)
    float* next_v = next_k + (size_t)Bsz * NKV * SEQ * HD;

    float *qbuf, *kbuf, *vbuf, *abuf;
    cudaGetSymbolAddress((void**)&qbuf, g_q);
    cudaGetSymbolAddress((void**)&kbuf, g_k);
    cudaGetSymbolAddress((void**)&vbuf, g_v);
    cudaGetSymbolAddress((void**)&abuf, g_attn);

    // Projections
    sgemm_kernel<<<dim3(EMB / GBN, BSxS / GBM), 256>>>(x, Wq, qbuf, BSxS, EMB, EMB);
    sgemm_kernel<<<dim3((NKV * HD) / GBN, BSxS / GBM), 256>>>(x, Wk, kbuf, BSxS, NKV * HD, EMB);
    sgemm_kernel<<<dim3((NKV * HD) / GBN, BSxS / GBM), 256>>>(x, Wv, vbuf, BSxS, NKV * HD, EMB);

    // RoPE + layout
    rope_q_kernel<<<(Bsz * SEQ * NH * 32) / 256, 256>>>(qbuf, cosp, sinp);
    rope_k_kernel<<<(Bsz * SEQ * NKV * 32) / 256, 256>>>(kbuf, cosp, sinp, next_k);
    vtrans_kernel<<<(Bsz * SEQ * NKV * HD) / 256, 256>>>(vbuf, next_v);

    // Attention (reads next_k/next_v written into d_out)
    attn_kernel<<<dim3(SEQ / 64, NH, Bsz), 64>>>(qbuf, next_k, next_v, abuf);

    // Output projection
    sgemm_kernel<<<dim3(EMB / GBN, BSxS / GBM), 256>>>(abuf, Wo, out, BSxS, EMB, EMB);
}

// round 2
// speedup vs baseline: 1.5085x; 1.5085x over previous
#include <cuda_runtime.h>
#include <cuda_bf16.h>
#include <cstdint>

// Problem constants
#define Bsz 2
#define SEQ 2048
#define EMB 2048
#define NH  32
#define NKV 8
#define HD  64
#define GRP 4          // NH / NKV
#define BSxS (Bsz*SEQ) // 4096

// ---------------- scratch (static device globals; no allocs allowed) --------
__device__ float g_q[(size_t)BSxS * EMB];      // x@Wq, roped+scaled in place, layout (B,S,H,D)
__device__ float g_k[(size_t)BSxS * NKV * HD]; // x@Wk raw, layout (B,S,KV,D)
__device__ float g_v[(size_t)BSxS * NKV * HD]; // x@Wv raw
__device__ float g_attn[(size_t)BSxS * EMB];   // attention output (B,S,H,D)=(B,S,E)

// ---------------- TF32 tensor-core GEMM: C[M,N] = A[M,K] @ B[K,N] -----------
// Block tile 128x128x32, 256 threads (8 warps), warp tile 32x64 via m16n8k8.
#define TM 128
#define TN 128
#define TK 32
#define AST 36   // As row stride (floats): 36 mod 32 = 4 -> conflict-free frags
#define BST 136  // Bs row stride: 136 mod 32 = 8 -> conflict-free frags

__device__ __forceinline__ uint32_t f2tf32(float x) {
    uint32_t y;
    asm("cvt.rna.tf32.f32 %0, %1;" : "=r"(y) : "f"(x));
    return y;
}

__device__ __forceinline__ void mma_tf32(float c[4], uint32_t a0, uint32_t a1,
                                         uint32_t a2, uint32_t a3,
                                         uint32_t b0, uint32_t b1) {
    asm volatile(
        "mma.sync.aligned.m16n8k8.row.col.f32.tf32.tf32.f32 "
        "{%0,%1,%2,%3}, {%4,%5,%6,%7}, {%8,%9}, {%0,%1,%2,%3};"
        : "+f"(c[0]), "+f"(c[1]), "+f"(c[2]), "+f"(c[3])
        : "r"(a0), "r"(a1), "r"(a2), "r"(a3), "r"(b0), "r"(b1));
}

__global__ __launch_bounds__(256) void tf32_gemm_kernel(
    const float* __restrict__ A, const float* __restrict__ B,
    float* __restrict__ C, int M, int N, int K)
{
    __shared__ uint32_t As[TM][AST];   // row-major M x K
    __shared__ uint32_t Bs[TK][BST];   // row-major K x N

    int tid  = threadIdx.x;
    int lane = tid & 31;
    int wid  = tid >> 5;
    int wm   = wid & 3;        // 4 warps along M
    int wn   = wid >> 2;       // 2 warps along N
    int bx   = blockIdx.x;     // N tile
    int by   = blockIdx.y;     // M tile

    const float* Ab = A + (size_t)by * TM * K;
    const float* Bb = B + (size_t)bx * TN;

    float acc[2][8][4];
#pragma unroll
    for (int i = 0; i < 2; i++)
#pragma unroll
        for (int j = 0; j < 8; j++)
#pragma unroll
            for (int r = 0; r < 4; r++) acc[i][j][r] = 0.f;

    int g  = lane >> 2;   // groupID 0..7
    int tg = lane & 3;    // 0..3
    int mrow = wm * 32 + g;
    int nbase = wn * 64 + g;

    // --- load tile 0 into smem ---
    {
#pragma unroll
        for (int i = 0; i < 4; i++) {
            int f = tid + i * 256;
            int row = f >> 3, col = (f & 7) << 2;           // A: 8 float4 per row
            float4 a = *(const float4*)(Ab + (size_t)row * K + col);
            As[row][col]     = f2tf32(a.x);
            As[row][col + 1] = f2tf32(a.y);
            As[row][col + 2] = f2tf32(a.z);
            As[row][col + 3] = f2tf32(a.w);
            int brow = f >> 5, bcol = (f & 31) << 2;        // B: 32 float4 per row
            float4 b = *(const float4*)(Bb + (size_t)brow * N + bcol);
            Bs[brow][bcol]     = f2tf32(b.x);
            Bs[brow][bcol + 1] = f2tf32(b.y);
            Bs[brow][bcol + 2] = f2tf32(b.z);
            Bs[brow][bcol + 3] = f2tf32(b.w);
        }
    }
    __syncthreads();

    int ntiles = K / TK;
    float4 pa[4], pb[4];
    for (int t = 0; t < ntiles; t++) {
        // prefetch next tile into registers
        if (t + 1 < ntiles) {
            int k0 = (t + 1) * TK;
#pragma unroll
            for (int i = 0; i < 4; i++) {
                int f = tid + i * 256;
                int row = f >> 3, col = (f & 7) << 2;
                pa[i] = *(const float4*)(Ab + (size_t)row * K + k0 + col);
                int brow = f >> 5, bcol = (f & 31) << 2;
                pb[i] = *(const float4*)(Bb + (size_t)(k0 + brow) * N + bcol);
            }
        }

        // compute
#pragma unroll
        for (int ks = 0; ks < 4; ks++) {
            int k0 = ks * 8;
            uint32_t af[2][4];
#pragma unroll
            for (int fm = 0; fm < 2; fm++) {
                int r = mrow + fm * 16;
                af[fm][0] = As[r][k0 + tg];
                af[fm][1] = As[r + 8][k0 + tg];
                af[fm][2] = As[r][k0 + tg + 4];
                af[fm][3] = As[r + 8][k0 + tg + 4];
            }
            uint32_t bf[8][2];
#pragma unroll
            for (int fn = 0; fn < 8; fn++) {
                int c = nbase + fn * 8;
                bf[fn][0] = Bs[k0 + tg][c];
                bf[fn][1] = Bs[k0 + tg + 4][c];
            }
#pragma unroll
            for (int fm = 0; fm < 2; fm++)
#pragma unroll
                for (int fn = 0; fn < 8; fn++)
                    mma_tf32(acc[fm][fn], af[fm][0], af[fm][1], af[fm][2], af[fm][3],
                             bf[fn][0], bf[fn][1]);
        }
        __syncthreads();

        if (t + 1 < ntiles) {
#pragma unroll
            for (int i = 0; i < 4; i++) {
                int f = tid + i * 256;
                int row = f >> 3, col = (f & 7) << 2;
                As[row][col]     = f2tf32(pa[i].x);
                As[row][col + 1] = f2tf32(pa[i].y);
                As[row][col + 2] = f2tf32(pa[i].z);
                As[row][col + 3] = f2tf32(pa[i].w);
                int brow = f >> 5, bcol = (f & 31) << 2;
                Bs[brow][bcol]     = f2tf32(pb[i].x);
                Bs[brow][bcol + 1] = f2tf32(pb[i].y);
                Bs[brow][bcol + 2] = f2tf32(pb[i].z);
                Bs[brow][bcol + 3] = f2tf32(pb[i].w);
            }
            __syncthreads();
        }
    }

    // epilogue
#pragma unroll
    for (int fm = 0; fm < 2; fm++) {
        int row0 = by * TM + wm * 32 + fm * 16 + g;
#pragma unroll
        for (int fn = 0; fn < 8; fn++) {
            int col = bx * TN + wn * 64 + fn * 8 + tg * 2;
            float2 lo = make_float2(acc[fm][fn][0], acc[fm][fn][1]);
            float2 hi = make_float2(acc[fm][fn][2], acc[fm][fn][3]);
            *(float2*)&C[(size_t)row0 * N + col]       = lo;
            *(float2*)&C[(size_t)(row0 + 8) * N + col] = hi;
        }
    }
}

// ---------------- RoPE on Q (in place, fold in 1/sqrt(HD) scale) ------------
__global__ void rope_q_kernel(float* __restrict__ q,
                              const float* __restrict__ cosp,
                              const float* __restrict__ sinp)
{
    int idx = blockIdx.x * blockDim.x + threadIdx.x;   // B*S*H*32 = 4194304
    if (idx >= Bsz * SEQ * NH * 32) return;
    int d  = idx & 31;
    int h  = (idx >> 5) & 31;
    int bs = idx >> 10;          // b*S+s
    int s  = bs & (SEQ - 1);
    float* base = q + ((size_t)bs * NH + h) * HD;
    float x1 = base[d];
    float x2 = base[d + 32];
    float c  = cosp[s * HD + d];
    float sn = sinp[s * HD + d];
    const float scale = 0.125f;  // 1/sqrt(64)
    base[d]      = (x1 * c - x2 * sn) * scale;
    base[d + 32] = (x2 * c + x1 * sn) * scale;
}

// ---------------- RoPE on K + transpose (B,S,KV,D)->(B,KV,S,D) -------------
__global__ void rope_k_kernel(const float* __restrict__ kraw,
                              const float* __restrict__ cosp,
                              const float* __restrict__ sinp,
                              float* __restrict__ nk)
{
    int idx = blockIdx.x * blockDim.x + threadIdx.x;   // B*S*KV*32 = 1048576
    if (idx >= Bsz * SEQ * NKV * 32) return;
    int d  = idx & 31;
    int kv = (idx >> 5) & 7;
    int bs = idx >> 8;           // b*S+s
    int s  = bs & (SEQ - 1);
    int b  = bs >> 11;
    const float* src = kraw + (size_t)bs * (NKV * HD) + kv * HD;
    float x1 = src[d];
    float x2 = src[d + 32];
    float c  = cosp[s * HD + d];
    float sn = sinp[s * HD + d];
    float* dst = nk + (((size_t)b * NKV + kv) * SEQ + s) * HD;
    dst[d]      = x1 * c - x2 * sn;
    dst[d + 32] = x2 * c + x1 * sn;
}

// ---------------- V transpose (B,S,KV,D)->(B,KV,S,D) ------------------------
__global__ void vtrans_kernel(const float* __restrict__ vraw, float* __restrict__ nv)
{
    int idx = blockIdx.x * blockDim.x + threadIdx.x;   // B*S*KV*D = 2097152
    if (idx >= Bsz * SEQ * NKV * HD) return;
    int d  = idx & 63;
    int kv = (idx >> 6) & 7;
    int bs = idx >> 9;
    int s  = bs & (SEQ - 1);
    int b  = bs >> 11;
    nv[(((size_t)b * NKV + kv) * SEQ + s) * HD + d] = vraw[(size_t)bs * (NKV * HD) + kv * HD + d];
}

// ---------------- Flash attention (causal), row-per-thread ------------------
// grid: (S/64, NH, B), block 64 threads. Q already scaled by 1/8.
__global__ __launch_bounds__(64) void attn_kernel(
    const float* __restrict__ q,    // (B,S,H,D)
    const float* __restrict__ kk,   // (B,KV,S,D)
    const float* __restrict__ vv,   // (B,KV,S,D)
    float* __restrict__ out)        // (B,S,H,D)
{
    int qt  = blockIdx.x;
    int h   = blockIdx.y;
    int b   = blockIdx.z;
    int kv  = h >> 2;               // GROUP=4
    int tid = threadIdx.x;
    int s0  = qt * 64 + tid;

    __shared__ float Ks[64][68];
    __shared__ float Vs[64][68];

    float qreg[HD];
    const float* qp = q + (((size_t)b * SEQ + s0) * NH + h) * HD;
#pragma unroll
    for (int i = 0; i < 16; i++) {
        float4 t = ((const float4*)qp)[i];
        qreg[4 * i]     = t.x;
        qreg[4 * i + 1] = t.y;
        qreg[4 * i + 2] = t.z;
        qreg[4 * i + 3] = t.w;
    }
    float o[HD];
#pragma unroll
    for (int i = 0; i < HD; i++) o[i] = 0.f;
    float m = -1e30f, l = 0.f;

    const float* kbase = kk + ((size_t)b * NKV + kv) * SEQ * HD;
    const float* vbase = vv + ((size_t)b * NKV + kv) * SEQ * HD;

    for (int kt = 0; kt <= qt; kt++) {
        __syncthreads();
        const float4* ksrc = (const float4*)(kbase + (size_t)kt * 64 * HD);
        const float4* vsrc = (const float4*)(vbase + (size_t)kt * 64 * HD);
#pragma unroll
        for (int i = 0; i < 16; i++) {
            int f   = i * 64 + tid;       // float4 index, 1024 total
            int row = f >> 4;             // 16 float4 per row
            int col = (f & 15) << 2;
            *(float4*)&Ks[row][col] = ksrc[f];
            *(float4*)&Vs[row][col] = vsrc[f];
        }
        __syncthreads();

        int jmax = (kt < qt) ? 64 : (tid + 1);
        for (int j = 0; j < jmax; j++) {
            float s = 0.f;
#pragma unroll
            for (int i = 0; i < 16; i++) {
                float4 kr = *(const float4*)&Ks[j][i * 4];
                s += qreg[4 * i] * kr.x + qreg[4 * i + 1] * kr.y +
                     qreg[4 * i + 2] * kr.z + qreg[4 * i + 3] * kr.w;
            }
            float mnew = fmaxf(m, s);
            float corr = __expf(m - mnew);
            float p    = __expf(s - mnew);
            l = l * corr + p;
            m = mnew;
#pragma unroll
            for (int i = 0; i < 16; i++) {
                float4 vr = *(const float4*)&Vs[j][i * 4];
                o[4 * i]     = o[4 * i]     * corr + p * vr.x;
                o[4 * i + 1] = o[4 * i + 1] * corr + p * vr.y;
                o[4 * i + 2] = o[4 * i + 2] * corr + p * vr.z;
                o[4 * i + 3] = o[4 * i + 3] * corr + p * vr.w;
            }
        }
    }

    float inv = 1.f / l;
    float* op = out + (((size_t)b * SEQ + s0) * NH + h) * HD;
#pragma unroll
    for (int i = 0; i < 16; i++) {
        float4 t;
        t.x = o[4 * i] * inv;
        t.y = o[4 * i + 1] * inv;
        t.z = o[4 * i + 2] * inv;
        t.w = o[4 * i + 3] * inv;
        ((float4*)op)[i] = t;
    }
}

// ---------------- launch -----------------------------------------------------
extern "C" void kernel_launch(void* const* d_in, const int* in_sizes, int n_in,
                              void* d_out, int out_size)
{
    const float* x    = (const float*)d_in[0];
    // d_in[1] = mask (causal triu k=1) — implemented analytically
    const float* cosp = (const float*)d_in[2];
    const float* sinp = (const float*)d_in[3];
    const float* Wq   = (const float*)d_in[4];
    const float* Wk   = (const float*)d_in[5];
    const float* Wv   = (const float*)d_in[6];
    const float* Wo   = (const float*)d_in[7];

    float* out    = (float*)d_out;
    float* next_k = out + (size_t)Bsz * SEQ * EMB;                 // (B,KV,S,D)
    float* next_v = next_k + (size_t)Bsz * NKV * SEQ * HD;

    float *qbuf, *kbuf, *vbuf, *abuf;
    cudaGetSymbolAddress((void**)&qbuf, g_q);
    cudaGetSymbolAddress((void**)&kbuf, g_k);
    cudaGetSymbolAddress((void**)&vbuf, g_v);
    cudaGetSymbolAddress((void**)&abuf, g_attn);

    // Projections (tf32 tensor cores)
    tf32_gemm_kernel<<<dim3(EMB / TN, BSxS / TM), 256>>>(x, Wq, qbuf, BSxS, EMB, EMB);
    tf32_gemm_kernel<<<dim3((NKV * HD) / TN, BSxS / TM), 256>>>(x, Wk, kbuf, BSxS, NKV * HD, EMB);
    tf32_gemm_kernel<<<dim3((NKV * HD) / TN, BSxS / TM), 256>>>(x, Wv, vbuf, BSxS, NKV * HD, EMB);

    // RoPE + layout
    rope_q_kernel<<<(Bsz * SEQ * NH * 32) / 256, 256>>>(qbuf, cosp, sinp);
    rope_k_kernel<<<(Bsz * SEQ * NKV * 32) / 256, 256>>>(kbuf, cosp, sinp, next_k);
    vtrans_kernel<<<(Bsz * SEQ * NKV * HD) / 256, 256>>>(vbuf, next_v);

    // Attention (reads next_k/next_v written into d_out)
    attn_kernel<<<dim3(SEQ / 64, NH, Bsz), 64>>>(qbuf, next_k, next_v, abuf);

    // Output projection
    tf32_gemm_kernel<<<dim3(EMB / TN, BSxS / TM), 256>>>(abuf, Wo, out, BSxS, EMB, EMB);
}

// round 5
// speedup vs baseline: 5.0122x; 3.3227x over previous
#include <cuda_runtime.h>
#include <cuda_fp16.h>
#include <cstdint>

// Problem constants
#define Bsz 2
#define SEQ 2048
#define EMB 2048
#define NH  32
#define NKV 8
#define HD  64
#define BSxS (Bsz*SEQ) // 4096

// ---------------- scratch ----------------------------------------------------
__device__ float g_q[(size_t)BSxS * EMB];      // x@Wq, roped+scaled (B,S,H,D)
__device__ float g_k[(size_t)BSxS * NKV * HD]; // x@Wk raw (B,S,KV,D)
__device__ float g_v[(size_t)BSxS * NKV * HD]; // x@Wv raw
__device__ float g_attn[(size_t)BSxS * EMB];   // attention output (B,S,H,D)

// ---------------- PTX helpers ------------------------------------------------
__device__ __forceinline__ uint32_t smem_u32(const void* p) {
    return (uint32_t)__cvta_generic_to_shared(p);
}
__device__ __forceinline__ void ldsm_x4(uint32_t& r0, uint32_t& r1, uint32_t& r2,
                                        uint32_t& r3, uint32_t addr) {
    asm volatile("ldmatrix.sync.aligned.m8n8.x4.shared.b16 {%0,%1,%2,%3},[%4];"
                 : "=r"(r0), "=r"(r1), "=r"(r2), "=r"(r3) : "r"(addr));
}
__device__ __forceinline__ void ldsm_x4t(uint32_t& r0, uint32_t& r1, uint32_t& r2,
                                         uint32_t& r3, uint32_t addr) {
    asm volatile("ldmatrix.sync.aligned.m8n8.x4.trans.shared.b16 {%0,%1,%2,%3},[%4];"
                 : "=r"(r0), "=r"(r1), "=r"(r2), "=r"(r3) : "r"(addr));
}
__device__ __forceinline__ void mma_f16(float c[4], uint32_t a0, uint32_t a1,
                                        uint32_t a2, uint32_t a3,
                                        uint32_t b0, uint32_t b1) {
    asm volatile(
        "mma.sync.aligned.m16n8k16.row.col.f32.f16.f16.f32 "
        "{%0,%1,%2,%3},{%4,%5,%6,%7},{%8,%9},{%0,%1,%2,%3};"
        : "+f"(c[0]), "+f"(c[1]), "+f"(c[2]), "+f"(c[3])
        : "r"(a0), "r"(a1), "r"(a2), "r"(a3), "r"(b0), "r"(b1));
}
__device__ __forceinline__ void st_half4(__half* p, float4 v) {
    __half2 h0 = __floats2half2_rn(v.x, v.y);
    __half2 h1 = __floats2half2_rn(v.z, v.w);
    uint2 u;
    u.x = *(uint32_t*)&h0;
    u.y = *(uint32_t*)&h1;
    *(uint2*)p = u;
}

// ---------------- fp16 tensor-core GEMM: C[M,N] = A[M,K] @ B[K,N] ------------
// 128x128x32 tiles, 256 threads (8 warps 4x2), warp tile 32x64, m16n8k16.
// blockIdx.z selects among up to 2 (B, C) pairs (for merged K/V projections).
#define TM 128
#define TN 128
#define TK 32
#define AST 40    // halves; row stride 80B = 5*16B (odd -> ldmatrix conflict-free)
#define BST 136   // halves; row stride 272B = 17*16B (odd)

__global__ __launch_bounds__(256) void h16_gemm(
    const float* __restrict__ A,
    const float* __restrict__ B0, float* __restrict__ C0,
    const float* __restrict__ B1, float* __restrict__ C1,
    int M, int N, int K)
{
    __shared__ __align__(16) __half As[TM][AST];   // row-major (m, k)
    __shared__ __align__(16) __half Bs[TK][BST];   // row-major (k, n)

    const float* B = (blockIdx.z == 0) ? B0 : B1;
    float* C       = (blockIdx.z == 0) ? C0 : C1;

    int tid = threadIdx.x, lane = tid & 31, wid = tid >> 5;
    int wm = wid & 3, wn = wid >> 2;
    int g = lane >> 2, tg = lane & 3;

    const float* Ab = A + (size_t)blockIdx.y * TM * K;
    const float* Bb = B + (size_t)blockIdx.x * TN;

    float acc[2][8][4];
#pragma unroll
    for (int i = 0; i < 2; i++)
#pragma unroll
        for (int j = 0; j < 8; j++)
#pragma unroll
            for (int r = 0; r < 4; r++) acc[i][j][r] = 0.f;

    // ldmatrix lane base addresses
    uint32_t aAddr[2], bAddr[4];
    {
        int arow = wm * 32 + (lane & 15);
        int acol = (lane >> 4) * 8;
        aAddr[0] = smem_u32(&As[arow][acol]);
        aAddr[1] = smem_u32(&As[arow + 16][acol]);
        int brow = ((lane >> 3) & 1) * 8 + (lane & 7);
        int bcol = wn * 64 + ((lane >> 4) & 1) * 8;
#pragma unroll
        for (int nb = 0; nb < 4; nb++)
            bAddr[nb] = smem_u32(&Bs[brow][bcol + nb * 16]);
    }

    int nt = K / TK;

    // load tile 0
#pragma unroll
    for (int i = 0; i < 4; i++) {
        int f = tid + i * 256;
        int r = f >> 3, c4 = f & 7;
        st_half4(&As[r][c4 * 4], *(const float4*)(Ab + (size_t)r * K + c4 * 4));
        int br = f >> 5, bc4 = f & 31;
        st_half4(&Bs[br][bc4 * 4], *(const float4*)(Bb + (size_t)br * N + bc4 * 4));
    }
    __syncthreads();

    for (int t = 0; t < nt; t++) {
        float4 pa[4], pb[4];
        if (t + 1 < nt) {
            int k0 = (t + 1) * TK;
#pragma unroll
            for (int i = 0; i < 4; i++) {
                int f = tid + i * 256;
                int r = f >> 3, c4 = f & 7;
                pa[i] = *(const float4*)(Ab + (size_t)r * K + k0 + c4 * 4);
                int br = f >> 5, bc4 = f & 31;
                pb[i] = *(const float4*)(Bb + (size_t)(k0 + br) * N + bc4 * 4);
            }
        }

#pragma unroll
        for (int ks = 0; ks < 2; ks++) {
            uint32_t af[2][4];
            ldsm_x4(af[0][0], af[0][1], af[0][2], af[0][3], aAddr[0] + ks * 32);
            ldsm_x4(af[1][0], af[1][1], af[1][2], af[1][3], aAddr[1] + ks * 32);
            uint32_t bf[8][2];
#pragma unroll
            for (int nb = 0; nb < 4; nb++) {
                uint32_t r0, r1, r2, r3;
                ldsm_x4t(r0, r1, r2, r3, bAddr[nb] + ks * (16 * BST * 2));
                bf[2 * nb][0] = r0; bf[2 * nb][1] = r1;
                bf[2 * nb + 1][0] = r2; bf[2 * nb + 1][1] = r3;
            }
#pragma unroll
            for (int mf = 0; mf < 2; mf++)
#pragma unroll
                for (int fn = 0; fn < 8; fn++)
                    mma_f16(acc[mf][fn], af[mf][0], af[mf][1], af[mf][2], af[mf][3],
                            bf[fn][0], bf[fn][1]);
        }
        __syncthreads();

        if (t + 1 < nt) {
#pragma unroll
            for (int i = 0; i < 4; i++) {
                int f = tid + i * 256;
                int r = f >> 3, c4 = f & 7;
                st_half4(&As[r][c4 * 4], pa[i]);
                int br = f >> 5, bc4 = f & 31;
                st_half4(&Bs[br][bc4 * 4], pb[i]);
            }
            __syncthreads();
        }
    }

    // epilogue
#pragma unroll
    for (int mf = 0; mf < 2; mf++) {
        int row0 = blockIdx.y * TM + wm * 32 + mf * 16 + g;
#pragma unroll
        for (int fn = 0; fn < 8; fn++) {
            int col = blockIdx.x * TN + wn * 64 + fn * 8 + tg * 2;
            *(float2*)&C[(size_t)row0 * N + col]       = make_float2(acc[mf][fn][0], acc[mf][fn][1]);
            *(float2*)&C[(size_t)(row0 + 8) * N + col] = make_float2(acc[mf][fn][2], acc[mf][fn][3]);
        }
    }
}

// ---------------- RoPE on Q (in place, fold in 1/sqrt(HD) scale) ------------
__global__ void rope_q_kernel(float* __restrict__ q,
                              const float* __restrict__ cosp,
                              const float* __restrict__ sinp)
{
    int idx = blockIdx.x * blockDim.x + threadIdx.x;
    if (idx >= Bsz * SEQ * NH * 32) return;
    int d  = idx & 31;
    int h  = (idx >> 5) & 31;
    int bs = idx >> 10;
    int s  = bs & (SEQ - 1);
    float* base = q + ((size_t)bs * NH + h) * HD;
    float x1 = base[d];
    float x2 = base[d + 32];
    float c  = cosp[s * HD + d];
    float sn = sinp[s * HD + d];
    const float scale = 0.125f;
    base[d]      = (x1 * c - x2 * sn) * scale;
    base[d + 32] = (x2 * c + x1 * sn) * scale;
}

// ---------------- RoPE on K + transpose (B,S,KV,D)->(B,KV,S,D) -------------
__global__ void rope_k_kernel(const float* __restrict__ kraw,
                              const float* __restrict__ cosp,
                              const float* __restrict__ sinp,
                              float* __restrict__ nk)
{
    int idx = blockIdx.x * blockDim.x + threadIdx.x;
    if (idx >= Bsz * SEQ * NKV * 32) return;
    int d  = idx & 31;
    int kv = (idx >> 5) & 7;
    int bs = idx >> 8;
    int s  = bs & (SEQ - 1);
    int b  = bs >> 11;
    const float* src = kraw + (size_t)bs * (NKV * HD) + kv * HD;
    float x1 = src[d];
    float x2 = src[d + 32];
    float c  = cosp[s * HD + d];
    float sn = sinp[s * HD + d];
    float* dst = nk + (((size_t)b * NKV + kv) * SEQ + s) * HD;
    dst[d]      = x1 * c - x2 * sn;
    dst[d + 32] = x2 * c + x1 * sn;
}

// ---------------- V transpose (B,S,KV,D)->(B,KV,S,D) ------------------------
__global__ void vtrans_kernel(const float* __restrict__ vraw, float* __restrict__ nv)
{
    int idx = blockIdx.x * blockDim.x + threadIdx.x;
    if (idx >= Bsz * SEQ * NKV * HD) return;
    int d  = idx & 63;
    int kv = (idx >> 6) & 7;
    int bs = idx >> 9;
    int s  = bs & (SEQ - 1);
    int b  = bs >> 11;
    nv[(((size_t)b * NKV + kv) * SEQ + s) * HD + d] = vraw[(size_t)bs * (NKV * HD) + kv * HD + d];
}

// ---------------- Tensor-core flash attention (causal) -----------------------
// grid (S/64, NH, B), 128 threads (4 warps, 16 q-rows each). Q pre-scaled.
#define QST 72    // halves; row stride 144B = 9*16B (odd -> conflict-free ldmatrix)

__global__ __launch_bounds__(128) void attn_h16(
    const float* __restrict__ q,    // (B,S,H,D) fp32, roped+scaled
    const float* __restrict__ kk,   // (B,KV,S,D) fp32
    const float* __restrict__ vv,   // (B,KV,S,D) fp32
    float* __restrict__ out)        // (B,S,H,D) fp32
{
    int qt = blockIdx.x, h = blockIdx.y, b = blockIdx.z;
    int kv = h >> 2;
    int tid = threadIdx.x, lane = tid & 31, w = tid >> 5;
    int g = lane >> 2, tg = lane & 3;

    __shared__ __align__(16) __half Qh[64][QST];
    __shared__ __align__(16) __half Qr[64][QST];
    __shared__ __align__(16) __half Ks[64][QST];
    __shared__ __align__(16) __half Vs[64][QST];

    const float* qbase = q + (((size_t)b * SEQ + (size_t)qt * 64) * NH + h) * HD;
    const float* kbase = kk + ((size_t)b * NKV + kv) * SEQ * HD;
    const float* vbase = vv + ((size_t)b * NKV + kv) * SEQ * HD;

    // Load Q tile (64x64), split into fp16 high + residual
#pragma unroll
    for (int i = 0; i < 8; i++) {
        int f = tid + i * 128;
        int r = f >> 4, c4 = f & 15;
        float4 v4 = *(const float4*)(qbase + (size_t)r * NH * HD + c4 * 4);
        __half hx = __float2half_rn(v4.x), hy = __float2half_rn(v4.y);
        __half hz = __float2half_rn(v4.z), hw = __float2half_rn(v4.w);
        __half2 h01 = __halves2half2(hx, hy);
        __half2 h23 = __halves2half2(hz, hw);
        uint2 uh;
        uh.x = *(uint32_t*)&h01; uh.y = *(uint32_t*)&h23;
        *(uint2*)&Qh[r][c4 * 4] = uh;
        float4 rr;
        rr.x = v4.x - __half2float(hx);
        rr.y = v4.y - __half2float(hy);
        rr.z = v4.z - __half2float(hz);
        rr.w = v4.w - __half2float(hw);
        st_half4(&Qr[r][c4 * 4], rr);
    }
    __syncthreads();

    // Q A-fragments (per warp: 16 rows x 64 d)
    uint32_t aqh[4][4], aqr[4][4];
    {
        int arow = w * 16 + (lane & 15);
        int acol = (lane >> 4) * 8;
        uint32_t bH = smem_u32(&Qh[arow][acol]);
        uint32_t bR = smem_u32(&Qr[arow][acol]);
#pragma unroll
        for (int ks = 0; ks < 4; ks++) {
            ldsm_x4(aqh[ks][0], aqh[ks][1], aqh[ks][2], aqh[ks][3], bH + ks * 32);
            ldsm_x4(aqr[ks][0], aqr[ks][1], aqr[ks][2], aqr[ks][3], bR + ks * 32);
        }
    }

    float oacc[8][4];
#pragma unroll
    for (int fn = 0; fn < 8; fn++)
#pragma unroll
        for (int r = 0; r < 4; r++) oacc[fn][r] = 0.f;
    float m0 = -1e30f, m1 = -1e30f, l0 = 0.f, l1 = 0.f;

    // ldmatrix lane addresses for K (non-trans) and V (trans)
    uint32_t kAddr[4], vAddr[4];
    {
        int krow = (lane & 15);
        int kcol = (lane >> 4) * 8;
#pragma unroll
        for (int nb = 0; nb < 4; nb++)
            kAddr[nb] = smem_u32(&Ks[nb * 16 + krow][kcol]);
        int vrow = ((lane >> 3) & 1) * 8 + (lane & 7);
        int vcol = ((lane >> 4) & 1) * 8;
#pragma unroll
        for (int nb = 0; nb < 4; nb++)
            vAddr[nb] = smem_u32(&Vs[vrow][vcol + nb * 16]);
    }

    int r0loc = w * 16 + g;
    int r1loc = r0loc + 8;

    for (int kt = 0; kt <= qt; kt++) {
        __syncthreads();
#pragma unroll
        for (int i = 0; i < 8; i++) {
            int f = tid + i * 128;
            int r = f >> 4, c4 = f & 15;
            st_half4(&Ks[r][c4 * 4],
                     *(const float4*)(kbase + (size_t)(kt * 64 + r) * HD + c4 * 4));
            st_half4(&Vs[r][c4 * 4],
                     *(const float4*)(vbase + (size_t)(kt * 64 + r) * HD + c4 * 4));
        }
        __syncthreads();

        // scores: S = Q @ K^T  (64x64 per block, 16x64 per warp)
        float s[8][4];
#pragma unroll
        for (int fn = 0; fn < 8; fn++)
#pragma unroll
            for (int r = 0; r < 4; r++) s[fn][r] = 0.f;

#pragma unroll
        for (int ks = 0; ks < 4; ks++) {
            uint32_t kb[8][2];
#pragma unroll
            for (int nb = 0; nb < 4; nb++) {
                uint32_t r0, r1, r2, r3;
                ldsm_x4(r0, r1, r2, r3, kAddr[nb] + ks * 32);
                kb[2 * nb][0] = r0; kb[2 * nb + 1][0] = r1;
                kb[2 * nb][1] = r2; kb[2 * nb + 1][1] = r3;
            }
#pragma unroll
            for (int fn = 0; fn < 8; fn++) {
                mma_f16(s[fn], aqh[ks][0], aqh[ks][1], aqh[ks][2], aqh[ks][3],
                        kb[fn][0], kb[fn][1]);
                mma_f16(s[fn], aqr[ks][0], aqr[ks][1], aqr[ks][2], aqr[ks][3],
                        kb[fn][0], kb[fn][1]);
            }
        }

        if (kt == qt) {
#pragma unroll
            for (int fn = 0; fn < 8; fn++) {
                int c = fn * 8 + 2 * tg;
                if (c > r0loc)     s[fn][0] = -1e30f;
                if (c + 1 > r0loc) s[fn][1] = -1e30f;
                if (c > r1loc)     s[fn][2] = -1e30f;
                if (c + 1 > r1loc) s[fn][3] = -1e30f;
            }
        }

        // online softmax
        float mx0 = -1e30f, mx1 = -1e30f;
#pragma unroll
        for (int fn = 0; fn < 8; fn++) {
            mx0 = fmaxf(mx0, fmaxf(s[fn][0], s[fn][1]));
            mx1 = fmaxf(mx1, fmaxf(s[fn][2], s[fn][3]));
        }
        mx0 = fmaxf(mx0, __shfl_xor_sync(0xffffffffu, mx0, 1));
        mx0 = fmaxf(mx0, __shfl_xor_sync(0xffffffffu, mx0, 2));
        mx1 = fmaxf(mx1, __shfl_xor_sync(0xffffffffu, mx1, 1));
        mx1 = fmaxf(mx1, __shfl_xor_sync(0xffffffffu, mx1, 2));
        float mn0 = fmaxf(m0, mx0), mn1 = fmaxf(m1, mx1);
        float c0 = __expf(m0 - mn0), c1 = __expf(m1 - mn1);
        m0 = mn0; m1 = mn1;

        float su0 = 0.f, su1 = 0.f;
        uint32_t pA[4][4];
#pragma unroll
        for (int fn = 0; fn < 8; fn++) {
            float e0 = __expf(s[fn][0] - mn0);
            float e1 = __expf(s[fn][1] - mn0);
            float e2 = __expf(s[fn][2] - mn1);
            float e3 = __expf(s[fn][3] - mn1);
            su0 += e0 + e1;
            su1 += e2 + e3;
            __half2 p01 = __floats2half2_rn(e0, e1);
            __half2 p23 = __floats2half2_rn(e2, e3);
            int kq = fn >> 1;
            int hi = (fn & 1) * 2;
            pA[kq][hi]     = *(uint32_t*)&p01;
            pA[kq][hi + 1] = *(uint32_t*)&p23;
        }
        su0 += __shfl_xor_sync(0xffffffffu, su0, 1);
        su0 += __shfl_xor_sync(0xffffffffu, su0, 2);
        su1 += __shfl_xor_sync(0xffffffffu, su1, 1);
        su1 += __shfl_xor_sync(0xffffffffu, su1, 2);
        l0 = l0 * c0 + su0;
        l1 = l1 * c1 + su1;

#pragma unroll
        for (int fn = 0; fn < 8; fn++) {
            oacc[fn][0] *= c0; oacc[fn][1] *= c0;
            oacc[fn][2] *= c1; oacc[fn][3] *= c1;
        }

        // O += P @ V
#pragma unroll
        for (int kq = 0; kq < 4; kq++) {
            uint32_t vb[8][2];
#pragma unroll
            for (int nb = 0; nb < 4; nb++) {
                uint32_t r0, r1, r2, r3;
                ldsm_x4t(r0, r1, r2, r3, vAddr[nb] + kq * (16 * QST * 2));
                vb[2 * nb][0] = r0; vb[2 * nb][1] = r1;
                vb[2 * nb + 1][0] = r2; vb[2 * nb + 1][1] = r3;
            }
#pragma unroll
            for (int fn = 0; fn < 8; fn++)
                mma_f16(oacc[fn], pA[kq][0], pA[kq][1], pA[kq][2], pA[kq][3],
                        vb[fn][0], vb[fn][1]);
        }
    }

    // epilogue
    float inv0 = 1.f / l0, inv1 = 1.f / l1;
    int row0 = qt * 64 + w * 16 + g;
    float* ob = out + (((size_t)b * SEQ + row0) * NH + h) * HD;
#pragma unroll
    for (int fn = 0; fn < 8; fn++) {
        int c = fn * 8 + 2 * tg;
        *(float2*)(ob + c) = make_float2(oacc[fn][0] * inv0, oacc[fn][1] * inv0);
        *(float2*)(ob + (size_t)8 * NH * HD + c) =
            make_float2(oacc[fn][2] * inv1, oacc[fn][3] * inv1);
    }
}

// ---------------- launch -----------------------------------------------------
extern "C" void kernel_launch(void* const* d_in, const int* in_sizes, int n_in,
                              void* d_out, int out_size)
{
    const float* x    = (const float*)d_in[0];
    // d_in[1] = mask (causal) — analytic
    const float* cosp = (const float*)d_in[2];
    const float* sinp = (const float*)d_in[3];
    const float* Wq   = (const float*)d_in[4];
    const float* Wk   = (const float*)d_in[5];
    const float* Wv   = (const float*)d_in[6];
    const float* Wo   = (const float*)d_in[7];

    float* out    = (float*)d_out;
    float* next_k = out + (size_t)Bsz * SEQ * EMB;
    float* next_v = next_k + (size_t)Bsz * NKV * SEQ * HD;

    float *qbuf, *kbuf, *vbuf, *abuf;
    cudaGetSymbolAddress((void**)&qbuf, g_q);
    cudaGetSymbolAddress((void**)&kbuf, g_k);
    cudaGetSymbolAddress((void**)&vbuf, g_v);
    cudaGetSymbolAddress((void**)&abuf, g_attn);

    // Projections (fp16 tensor cores, fp32 accumulate)
    h16_gemm<<<dim3(EMB / TN, BSxS / TM, 1), 256>>>(x, Wq, qbuf, Wq, qbuf,
                                                    BSxS, EMB, EMB);
    // K and V projections merged into one launch (z selects weight/output)
    h16_gemm<<<dim3((NKV * HD) / TN, BSxS / TM, 2), 256>>>(x, Wk, kbuf, Wv, vbuf,
                                                           BSxS, NKV * HD, EMB);

    // RoPE + layout
    rope_q_kernel<<<(Bsz * SEQ * NH * 32) / 256, 256>>>(qbuf, cosp, sinp);
    rope_k_kernel<<<(Bsz * SEQ * NKV * 32) / 256, 256>>>(kbuf, cosp, sinp, next_k);
    vtrans_kernel<<<(Bsz * SEQ * NKV * HD) / 256, 256>>>(vbuf, next_v);

    // Tensor-core flash attention
    attn_h16<<<dim3(SEQ / 64, NH, Bsz), 128>>>(qbuf, next_k, next_v, abuf);

    // Output projection
    h16_gemm<<<dim3(EMB / TN, BSxS / TM, 1), 256>>>(abuf, Wo, out, Wo, out,
                                                    BSxS, EMB, EMB);
}

// round 6
// speedup vs baseline: 6.8969x; 1.3760x over previous
#include <cuda_runtime.h>
#include <cuda_fp16.h>
#include <cstdint>

// Problem constants
#define Bsz 2
#define SEQ 2048
#define EMB 2048
#define NH  32
#define NKV 8
#define HD  64
#define BSxS (Bsz*SEQ) // 4096

// ---------------- scratch ----------------------------------------------------
__device__ float  g_q[(size_t)BSxS * EMB];          // x@Wq fp32, roped+scaled (B,S,H,D)
__device__ float  g_k[(size_t)BSxS * NKV * HD];     // x@Wk raw fp32 (B,S,KV,D)
__device__ float  g_v[(size_t)BSxS * NKV * HD];     // x@Wv raw fp32
__device__ __half g_xh[(size_t)BSxS * EMB];         // x in fp16
__device__ __half g_wqh[(size_t)EMB * EMB];
__device__ __half g_wkh[(size_t)EMB * NKV * HD];
__device__ __half g_wvh[(size_t)EMB * NKV * HD];
__device__ __half g_woh[(size_t)EMB * EMB];
__device__ __half g_ah[(size_t)BSxS * EMB];         // attention output fp16 (B,S,H,D)

// ---------------- PTX helpers ------------------------------------------------
__device__ __forceinline__ uint32_t smem_u32(const void* p) {
    return (uint32_t)__cvta_generic_to_shared(p);
}
__device__ __forceinline__ void ldsm_x4(uint32_t& r0, uint32_t& r1, uint32_t& r2,
                                        uint32_t& r3, uint32_t addr) {
    asm volatile("ldmatrix.sync.aligned.m8n8.x4.shared.b16 {%0,%1,%2,%3},[%4];"
                 : "=r"(r0), "=r"(r1), "=r"(r2), "=r"(r3) : "r"(addr));
}
__device__ __forceinline__ void ldsm_x4t(uint32_t& r0, uint32_t& r1, uint32_t& r2,
                                         uint32_t& r3, uint32_t addr) {
    asm volatile("ldmatrix.sync.aligned.m8n8.x4.trans.shared.b16 {%0,%1,%2,%3},[%4];"
                 : "=r"(r0), "=r"(r1), "=r"(r2), "=r"(r3) : "r"(addr));
}
__device__ __forceinline__ void mma_f16(float c[4], uint32_t a0, uint32_t a1,
                                        uint32_t a2, uint32_t a3,
                                        uint32_t b0, uint32_t b1) {
    asm volatile(
        "mma.sync.aligned.m16n8k16.row.col.f32.f16.f16.f32 "
        "{%0,%1,%2,%3},{%4,%5,%6,%7},{%8,%9},{%0,%1,%2,%3};"
        : "+f"(c[0]), "+f"(c[1]), "+f"(c[2]), "+f"(c[3])
        : "r"(a0), "r"(a1), "r"(a2), "r"(a3), "r"(b0), "r"(b1));
}
__device__ __forceinline__ void st_half4(__half* p, float4 v) {
    __half2 h0 = __floats2half2_rn(v.x, v.y);
    __half2 h1 = __floats2half2_rn(v.z, v.w);
    uint2 u;
    u.x = *(uint32_t*)&h0;
    u.y = *(uint32_t*)&h1;
    *(uint2*)p = u;
}
__device__ __forceinline__ void cp16(uint32_t dst, const void* src) {
    asm volatile("cp.async.ca.shared.global [%0], [%1], 16;" :: "r"(dst), "l"(src));
}
__device__ __forceinline__ void cp_commit() {
    asm volatile("cp.async.commit_group;" ::: "memory");
}
template <int N>
__device__ __forceinline__ void cp_wait() {
    asm volatile("cp.async.wait_group %0;" :: "n"(N) : "memory");
}

// ---------------- fp32 -> fp16 conversion ------------------------------------
__global__ void cvt_f2h(const float* __restrict__ src, __half* __restrict__ dst, int n)
{
    int i = (blockIdx.x * blockDim.x + threadIdx.x) * 4;
    if (i < n) st_half4(dst + i, *(const float4*)(src + i));
}

// ---------------- fp16 cp.async pipelined GEMM: C[M,N] = A@B -----------------
// 128x128x32 tiles, 256 threads (8 warps 4x2), warp tile 32x64, m16n8k16.
// 3-stage cp.async pipeline. blockIdx.z selects (B,C) pair (merged K/V).
#define TM 128
#define TN 128
#define TK 32
#define AST 40    // halves; 80B row stride -> (5r+c)%8 conflict-free
#define BST 136   // halves; 272B row stride -> (17r+c)%8 conflict-free
#define STG 3
#define ASZ (TM * AST * 2)   // stage size bytes: 10240
#define BSZ (TK * BST * 2)   // 8704

__global__ __launch_bounds__(256) void h16_gemm(
    const __half* __restrict__ A,
    const __half* __restrict__ B0, float* __restrict__ C0,
    const __half* __restrict__ B1, float* __restrict__ C1,
    int M, int N, int K)
{
    __shared__ __align__(16) __half As[STG][TM][AST];
    __shared__ __align__(16) __half Bs[STG][TK][BST];

    const __half* B = (blockIdx.z == 0) ? B0 : B1;
    float* C        = (blockIdx.z == 0) ? C0 : C1;

    int tid = threadIdx.x, lane = tid & 31, wid = tid >> 5;
    int wm = wid & 3, wn = wid >> 2;
    int g = lane >> 2, tg = lane & 3;

    const __half* Ab = A + (size_t)blockIdx.y * TM * K;
    const __half* Bb = B + (size_t)blockIdx.x * TN;

    float acc[2][8][4];
#pragma unroll
    for (int i = 0; i < 2; i++)
#pragma unroll
        for (int j = 0; j < 8; j++)
#pragma unroll
            for (int r = 0; r < 4; r++) acc[i][j][r] = 0.f;

    // per-thread cp.async chunk coordinates (16B = 8 halves per chunk)
    int ar0 = tid >> 2, ac0 = (tid & 3) * 8;                // A chunks 0..255
    int ar1 = (tid + 256) >> 2, ac1 = ((tid + 256) & 3) * 8;
    int br0 = tid >> 4, bc0 = (tid & 15) * 8;               // B chunks 0..255
    int br1 = (tid + 256) >> 4, bc1 = ((tid + 256) & 15) * 8;
    uint32_t aD0 = smem_u32(&As[0][ar0][ac0]);
    uint32_t aD1 = smem_u32(&As[0][ar1][ac1]);
    uint32_t bD0 = smem_u32(&Bs[0][br0][bc0]);
    uint32_t bD1 = smem_u32(&Bs[0][br1][bc1]);

    // ldmatrix lane base addresses (stage 0)
    uint32_t aAddr[2], bAddr[4];
    {
        int arow = wm * 32 + (lane & 15);
        int acol = (lane >> 4) * 8;
        aAddr[0] = smem_u32(&As[0][arow][acol]);
        aAddr[1] = smem_u32(&As[0][arow + 16][acol]);
        int brow = ((lane >> 3) & 1) * 8 + (lane & 7);
        int bcol = wn * 64 + ((lane >> 4) & 1) * 8;
#pragma unroll
        for (int nb = 0; nb < 4; nb++)
            bAddr[nb] = smem_u32(&Bs[0][brow][bcol + nb * 16]);
    }

    int nt = K / TK;

    // prologue: issue stages 0 and 1
#pragma unroll
    for (int p = 0; p < 2; p++) {
        int k0 = p * TK;
        cp16(aD0 + p * ASZ, Ab + (size_t)ar0 * K + k0 + ac0);
        cp16(aD1 + p * ASZ, Ab + (size_t)ar1 * K + k0 + ac1);
        cp16(bD0 + p * BSZ, Bb + (size_t)(k0 + br0) * N + bc0);
        cp16(bD1 + p * BSZ, Bb + (size_t)(k0 + br1) * N + bc1);
        cp_commit();
    }

    int st = 0;
    for (int t = 0; t < nt; t++) {
        cp_wait<1>();
        __syncthreads();

        uint32_t aOff = (uint32_t)(st * ASZ);
        uint32_t bOff = (uint32_t)(st * BSZ);
#pragma unroll
        for (int ks = 0; ks < 2; ks++) {
            uint32_t af[2][4];
            ldsm_x4(af[0][0], af[0][1], af[0][2], af[0][3], aAddr[0] + aOff + ks * 32);
            ldsm_x4(af[1][0], af[1][1], af[1][2], af[1][3], aAddr[1] + aOff + ks * 32);
            uint32_t bf[8][2];
#pragma unroll
            for (int nb = 0; nb < 4; nb++) {
                uint32_t r0, r1, r2, r3;
                ldsm_x4t(r0, r1, r2, r3, bAddr[nb] + bOff + ks * (16 * BST * 2));
                bf[2 * nb][0] = r0; bf[2 * nb][1] = r1;
                bf[2 * nb + 1][0] = r2; bf[2 * nb + 1][1] = r3;
            }
#pragma unroll
            for (int mf = 0; mf < 2; mf++)
#pragma unroll
                for (int fn = 0; fn < 8; fn++)
                    mma_f16(acc[mf][fn], af[mf][0], af[mf][1], af[mf][2], af[mf][3],
                            bf[fn][0], bf[fn][1]);
        }
        __syncthreads();

        // issue tile t+2 into stage (t+2)%3 (the stage just freed)
        if (t + 2 < nt) {
            int ns = (st + 2) % STG;
            int k0 = (t + 2) * TK;
            cp16(aD0 + ns * ASZ, Ab + (size_t)ar0 * K + k0 + ac0);
            cp16(aD1 + ns * ASZ, Ab + (size_t)ar1 * K + k0 + ac1);
            cp16(bD0 + ns * BSZ, Bb + (size_t)(k0 + br0) * N + bc0);
            cp16(bD1 + ns * BSZ, Bb + (size_t)(k0 + br1) * N + bc1);
        }
        cp_commit();   // commit every iteration (possibly empty) to keep wait counts exact
        st = (st + 1) % STG;
    }

    // epilogue
#pragma unroll
    for (int mf = 0; mf < 2; mf++) {
        int row0 = blockIdx.y * TM + wm * 32 + mf * 16 + g;
#pragma unroll
        for (int fn = 0; fn < 8; fn++) {
            int col = blockIdx.x * TN + wn * 64 + fn * 8 + tg * 2;
            *(float2*)&C[(size_t)row0 * N + col]       = make_float2(acc[mf][fn][0], acc[mf][fn][1]);
            *(float2*)&C[(size_t)(row0 + 8) * N + col] = make_float2(acc[mf][fn][2], acc[mf][fn][3]);
        }
    }
}

// ---------------- RoPE on Q (in place, fold in 1/sqrt(HD) scale) ------------
__global__ void rope_q_kernel(float* __restrict__ q,
                              const float* __restrict__ cosp,
                              const float* __restrict__ sinp)
{
    int idx = blockIdx.x * blockDim.x + threadIdx.x;
    if (idx >= Bsz * SEQ * NH * 32) return;
    int d  = idx & 31;
    int h  = (idx >> 5) & 31;
    int bs = idx >> 10;
    int s  = bs & (SEQ - 1);
    float* base = q + ((size_t)bs * NH + h) * HD;
    float x1 = base[d];
    float x2 = base[d + 32];
    float c  = cosp[s * HD + d];
    float sn = sinp[s * HD + d];
    const float scale = 0.125f;
    base[d]      = (x1 * c - x2 * sn) * scale;
    base[d + 32] = (x2 * c + x1 * sn) * scale;
}

// ---------------- RoPE on K + transpose (B,S,KV,D)->(B,KV,S,D) -------------
__global__ void rope_k_kernel(const float* __restrict__ kraw,
                              const float* __restrict__ cosp,
                              const float* __restrict__ sinp,
                              float* __restrict__ nk)
{
    int idx = blockIdx.x * blockDim.x + threadIdx.x;
    if (idx >= Bsz * SEQ * NKV * 32) return;
    int d  = idx & 31;
    int kv = (idx >> 5) & 7;
    int bs = idx >> 8;
    int s  = bs & (SEQ - 1);
    int b  = bs >> 11;
    const float* src = kraw + (size_t)bs * (NKV * HD) + kv * HD;
    float x1 = src[d];
    float x2 = src[d + 32];
    float c  = cosp[s * HD + d];
    float sn = sinp[s * HD + d];
    float* dst = nk + (((size_t)b * NKV + kv) * SEQ + s) * HD;
    dst[d]      = x1 * c - x2 * sn;
    dst[d + 32] = x2 * c + x1 * sn;
}

// ---------------- V transpose (B,S,KV,D)->(B,KV,S,D) ------------------------
__global__ void vtrans_kernel(const float* __restrict__ vraw, float* __restrict__ nv)
{
    int idx = blockIdx.x * blockDim.x + threadIdx.x;
    if (idx >= Bsz * SEQ * NKV * HD) return;
    int d  = idx & 63;
    int kv = (idx >> 6) & 7;
    int bs = idx >> 9;
    int s  = bs & (SEQ - 1);
    int b  = bs >> 11;
    nv[(((size_t)b * NKV + kv) * SEQ + s) * HD + d] = vraw[(size_t)bs * (NKV * HD) + kv * HD + d];
}

// ---------------- Tensor-core flash attention (causal) -----------------------
// grid (S/64, NH, B), 128 threads (4 warps, 16 q-rows each). Q pre-scaled.
// Output written as fp16 (feeds Wo GEMM only).
#define QST 72    // halves; 144B row stride (odd multiple of 16B -> conflict-free)

__global__ __launch_bounds__(128) void attn_h16(
    const float* __restrict__ q,    // (B,S,H,D) fp32, roped+scaled
    const float* __restrict__ kk,   // (B,KV,S,D) fp32
    const float* __restrict__ vv,   // (B,KV,S,D) fp32
    __half* __restrict__ out)       // (B,S,H,D) fp16
{
    int qt = blockIdx.x, h = blockIdx.y, b = blockIdx.z;
    int kv = h >> 2;
    int tid = threadIdx.x, lane = tid & 31, w = tid >> 5;
    int g = lane >> 2, tg = lane & 3;

    __shared__ __align__(16) __half Qh[64][QST];
    __shared__ __align__(16) __half Qr[64][QST];
    __shared__ __align__(16) __half Ks[64][QST];
    __shared__ __align__(16) __half Vs[64][QST];

    const float* qbase = q + (((size_t)b * SEQ + (size_t)qt * 64) * NH + h) * HD;
    const float* kbase = kk + ((size_t)b * NKV + kv) * SEQ * HD;
    const float* vbase = vv + ((size_t)b * NKV + kv) * SEQ * HD;

    // Load Q tile (64x64), split into fp16 high + residual
#pragma unroll
    for (int i = 0; i < 8; i++) {
        int f = tid + i * 128;
        int r = f >> 4, c4 = f & 15;
        float4 v4 = *(const float4*)(qbase + (size_t)r * NH * HD + c4 * 4);
        __half hx = __float2half_rn(v4.x), hy = __float2half_rn(v4.y);
        __half hz = __float2half_rn(v4.z), hw = __float2half_rn(v4.w);
        __half2 h01 = __halves2half2(hx, hy);
        __half2 h23 = __halves2half2(hz, hw);
        uint2 uh;
        uh.x = *(uint32_t*)&h01; uh.y = *(uint32_t*)&h23;
        *(uint2*)&Qh[r][c4 * 4] = uh;
        float4 rr;
        rr.x = v4.x - __half2float(hx);
        rr.y = v4.y - __half2float(hy);
        rr.z = v4.z - __half2float(hz);
        rr.w = v4.w - __half2float(hw);
        st_half4(&Qr[r][c4 * 4], rr);
    }
    __syncthreads();

    // Q A-fragments (per warp: 16 rows x 64 d)
    uint32_t aqh[4][4], aqr[4][4];
    {
        int arow = w * 16 + (lane & 15);
        int acol = (lane >> 4) * 8;
        uint32_t bH = smem_u32(&Qh[arow][acol]);
        uint32_t bR = smem_u32(&Qr[arow][acol]);
#pragma unroll
        for (int ks = 0; ks < 4; ks++) {
            ldsm_x4(aqh[ks][0], aqh[ks][1], aqh[ks][2], aqh[ks][3], bH + ks * 32);
            ldsm_x4(aqr[ks][0], aqr[ks][1], aqr[ks][2], aqr[ks][3], bR + ks * 32);
        }
    }

    float oacc[8][4];
#pragma unroll
    for (int fn = 0; fn < 8; fn++)
#pragma unroll
        for (int r = 0; r < 4; r++) oacc[fn][r] = 0.f;
    float m0 = -1e30f, m1 = -1e30f, l0 = 0.f, l1 = 0.f;

    // ldmatrix lane addresses for K (non-trans) and V (trans)
    uint32_t kAddr[4], vAddr[4];
    {
        int krow = (lane & 15);
        int kcol = (lane >> 4) * 8;
#pragma unroll
        for (int nb = 0; nb < 4; nb++)
            kAddr[nb] = smem_u32(&Ks[nb * 16 + krow][kcol]);
        int vrow = ((lane >> 3) & 1) * 8 + (lane & 7);
        int vcol = ((lane >> 4) & 1) * 8;
#pragma unroll
        for (int nb = 0; nb < 4; nb++)
            vAddr[nb] = smem_u32(&Vs[vrow][vcol + nb * 16]);
    }

    int r0loc = w * 16 + g;
    int r1loc = r0loc + 8;

    for (int kt = 0; kt <= qt; kt++) {
        __syncthreads();
#pragma unroll
        for (int i = 0; i < 8; i++) {
            int f = tid + i * 128;
            int r = f >> 4, c4 = f & 15;
            st_half4(&Ks[r][c4 * 4],
                     *(const float4*)(kbase + (size_t)(kt * 64 + r) * HD + c4 * 4));
            st_half4(&Vs[r][c4 * 4],
                     *(const float4*)(vbase + (size_t)(kt * 64 + r) * HD + c4 * 4));
        }
        __syncthreads();

        // scores: S = Q @ K^T  (64x64 per block, 16x64 per warp)
        float s[8][4];
#pragma unroll
        for (int fn = 0; fn < 8; fn++)
#pragma unroll
            for (int r = 0; r < 4; r++) s[fn][r] = 0.f;

#pragma unroll
        for (int ks = 0; ks < 4; ks++) {
            uint32_t kb[8][2];
#pragma unroll
            for (int nb = 0; nb < 4; nb++) {
                uint32_t r0, r1, r2, r3;
                ldsm_x4(r0, r1, r2, r3, kAddr[nb] + ks * 32);
                kb[2 * nb][0] = r0; kb[2 * nb + 1][0] = r1;
                kb[2 * nb][1] = r2; kb[2 * nb + 1][1] = r3;
            }
#pragma unroll
            for (int fn = 0; fn < 8; fn++) {
                mma_f16(s[fn], aqh[ks][0], aqh[ks][1], aqh[ks][2], aqh[ks][3],
                        kb[fn][0], kb[fn][1]);
                mma_f16(s[fn], aqr[ks][0], aqr[ks][1], aqr[ks][2], aqr[ks][3],
                        kb[fn][0], kb[fn][1]);
            }
        }

        if (kt == qt) {
#pragma unroll
            for (int fn = 0; fn < 8; fn++) {
                int c = fn * 8 + 2 * tg;
                if (c > r0loc)     s[fn][0] = -1e30f;
                if (c + 1 > r0loc) s[fn][1] = -1e30f;
                if (c > r1loc)     s[fn][2] = -1e30f;
                if (c + 1 > r1loc) s[fn][3] = -1e30f;
            }
        }

        // online softmax
        float mx0 = -1e30f, mx1 = -1e30f;
#pragma unroll
        for (int fn = 0; fn < 8; fn++) {
            mx0 = fmaxf(mx0, fmaxf(s[fn][0], s[fn][1]));
            mx1 = fmaxf(mx1, fmaxf(s[fn][2], s[fn][3]));
        }
        mx0 = fmaxf(mx0, __shfl_xor_sync(0xffffffffu, mx0, 1));
        mx0 = fmaxf(mx0, __shfl_xor_sync(0xffffffffu, mx0, 2));
        mx1 = fmaxf(mx1, __shfl_xor_sync(0xffffffffu, mx1, 1));
        mx1 = fmaxf(mx1, __shfl_xor_sync(0xffffffffu, mx1, 2));
        float mn0 = fmaxf(m0, mx0), mn1 = fmaxf(m1, mx1);
        float c0 = __expf(m0 - mn0), c1 = __expf(m1 - mn1);
        m0 = mn0; m1 = mn1;

        float su0 = 0.f, su1 = 0.f;
        uint32_t pA[4][4];
#pragma unroll
        for (int fn = 0; fn < 8; fn++) {
            float e0 = __expf(s[fn][0] - mn0);
            float e1 = __expf(s[fn][1] - mn0);
            float e2 = __expf(s[fn][2] - mn1);
            float e3 = __expf(s[fn][3] - mn1);
            su0 += e0 + e1;
            su1 += e2 + e3;
            __half2 p01 = __floats2half2_rn(e0, e1);
            __half2 p23 = __floats2half2_rn(e2, e3);
            int kq = fn >> 1;
            int hi = (fn & 1) * 2;
            pA[kq][hi]     = *(uint32_t*)&p01;
            pA[kq][hi + 1] = *(uint32_t*)&p23;
        }
        su0 += __shfl_xor_sync(0xffffffffu, su0, 1);
        su0 += __shfl_xor_sync(0xffffffffu, su0, 2);
        su1 += __shfl_xor_sync(0xffffffffu, su1, 1);
        su1 += __shfl_xor_sync(0xffffffffu, su1, 2);
        l0 = l0 * c0 + su0;
        l1 = l1 * c1 + su1;

#pragma unroll
        for (int fn = 0; fn < 8; fn++) {
            oacc[fn][0] *= c0; oacc[fn][1] *= c0;
            oacc[fn][2] *= c1; oacc[fn][3] *= c1;
        }

        // O += P @ V
#pragma unroll
        for (int kq = 0; kq < 4; kq++) {
            uint32_t vb[8][2];
#pragma unroll
            for (int nb = 0; nb < 4; nb++) {
                uint32_t r0, r1, r2, r3;
                ldsm_x4t(r0, r1, r2, r3, vAddr[nb] + kq * (16 * QST * 2));
                vb[2 * nb][0] = r0; vb[2 * nb][1] = r1;
                vb[2 * nb + 1][0] = r2; vb[2 * nb + 1][1] = r3;
            }
#pragma unroll
            for (int fn = 0; fn < 8; fn++)
                mma_f16(oacc[fn], pA[kq][0], pA[kq][1], pA[kq][2], pA[kq][3],
                        vb[fn][0], vb[fn][1]);
        }
    }

    // epilogue (fp16 out)
    float inv0 = 1.f / l0, inv1 = 1.f / l1;
    int row0 = qt * 64 + w * 16 + g;
    __half* ob = out + (((size_t)b * SEQ + row0) * NH + h) * HD;
#pragma unroll
    for (int fn = 0; fn < 8; fn++) {
        int c = fn * 8 + 2 * tg;
        __half2 lo = __floats2half2_rn(oacc[fn][0] * inv0, oacc[fn][1] * inv0);
        __half2 hi = __floats2half2_rn(oacc[fn][2] * inv1, oacc[fn][3] * inv1);
        *(__half2*)(ob + c) = lo;
        *(__half2*)(ob + (size_t)8 * NH * HD + c) = hi;
    }
}

// ---------------- launch -----------------------------------------------------
extern "C" void kernel_launch(void* const* d_in, const int* in_sizes, int n_in,
                              void* d_out, int out_size)
{
    const float* x    = (const float*)d_in[0];
    // d_in[1] = mask (causal) — analytic
    const float* cosp = (const float*)d_in[2];
    const float* sinp = (const float*)d_in[3];
    const float* Wq   = (const float*)d_in[4];
    const float* Wk   = (const float*)d_in[5];
    const float* Wv   = (const float*)d_in[6];
    const float* Wo   = (const float*)d_in[7];

    float* out    = (float*)d_out;
    float* next_k = out + (size_t)Bsz * SEQ * EMB;
    float* next_v = next_k + (size_t)Bsz * NKV * SEQ * HD;

    float *qbuf, *kbuf, *vbuf;
    __half *xh, *wqh, *wkh, *wvh, *woh, *ah;
    cudaGetSymbolAddress((void**)&qbuf, g_q);
    cudaGetSymbolAddress((void**)&kbuf, g_k);
    cudaGetSymbolAddress((void**)&vbuf, g_v);
    cudaGetSymbolAddress((void**)&xh,  g_xh);
    cudaGetSymbolAddress((void**)&wqh, g_wqh);
    cudaGetSymbolAddress((void**)&wkh, g_wkh);
    cudaGetSymbolAddress((void**)&wvh, g_wvh);
    cudaGetSymbolAddress((void**)&woh, g_woh);
    cudaGetSymbolAddress((void**)&ah,  g_ah);

    // fp32 -> fp16 conversions
    cvt_f2h<<<(BSxS * EMB) / 1024, 256>>>(x, xh, BSxS * EMB);
    cvt_f2h<<<(EMB * EMB) / 1024, 256>>>(Wq, wqh, EMB * EMB);
    cvt_f2h<<<(EMB * NKV * HD) / 1024, 256>>>(Wk, wkh, EMB * NKV * HD);
    cvt_f2h<<<(EMB * NKV * HD) / 1024, 256>>>(Wv, wvh, EMB * NKV * HD);
    cvt_f2h<<<(EMB * EMB) / 1024, 256>>>(Wo, woh, EMB * EMB);

    // Projections (fp16 tensor cores, cp.async pipeline)
    h16_gemm<<<dim3(EMB / TN, BSxS / TM, 1), 256>>>(xh, wqh, qbuf, wqh, qbuf,
                                                    BSxS, EMB, EMB);
    h16_gemm<<<dim3((NKV * HD) / TN, BSxS / TM, 2), 256>>>(xh, wkh, kbuf, wvh, vbuf,
                                                           BSxS, NKV * HD, EMB);

    // RoPE + layout
    rope_q_kernel<<<(Bsz * SEQ * NH * 32) / 256, 256>>>(qbuf, cosp, sinp);
    rope_k_kernel<<<(Bsz * SEQ * NKV * 32) / 256, 256>>>(kbuf, cosp, sinp, next_k);
    vtrans_kernel<<<(Bsz * SEQ * NKV * HD) / 256, 256>>>(vbuf, next_v);

    // Tensor-core flash attention (fp16 output straight into Wo GEMM input)
    attn_h16<<<dim3(SEQ / 64, NH, Bsz), 128>>>(qbuf, next_k, next_v, ah);

    // Output projection
    h16_gemm<<<dim3(EMB / TN, BSxS / TM, 1), 256>>>(ah, woh, out, woh, out,
                                                    BSxS, EMB, EMB);
}

// round 7
// speedup vs baseline: 7.5541x; 1.0953x over previous
#include <cuda_runtime.h>
#include <cuda_fp16.h>
#include <cstdint>

// Problem constants
#define Bsz 2
#define SEQ 2048
#define EMB 2048
#define NH  32
#define NKV 8
#define HD  64
#define BSxS (Bsz*SEQ) // 4096

// ---------------- scratch ----------------------------------------------------
__device__ float  g_q[(size_t)BSxS * EMB];          // x@Wq fp32 (B,S,H,D)
__device__ float  g_k[(size_t)BSxS * NKV * HD];     // x@Wk raw fp32 (B,S,KV,D)
__device__ float  g_v[(size_t)BSxS * NKV * HD];     // x@Wv raw fp32
__device__ __half g_xh[(size_t)BSxS * EMB];         // x fp16
__device__ __half g_wqh[(size_t)EMB * EMB];
__device__ __half g_wkh[(size_t)EMB * NKV * HD];
__device__ __half g_wvh[(size_t)EMB * NKV * HD];
__device__ __half g_woh[(size_t)EMB * EMB];
__device__ __half g_qh[(size_t)BSxS * EMB];         // roped+scaled Q fp16 (B,S,H,D)
__device__ __half g_kh[(size_t)Bsz * NKV * SEQ * HD]; // roped K fp16 (B,KV,S,D)
__device__ __half g_vh[(size_t)Bsz * NKV * SEQ * HD]; // V fp16 (B,KV,S,D)
__device__ __half g_ah[(size_t)BSxS * EMB];         // attention out fp16 (B,S,H,D)

// ---------------- PTX helpers ------------------------------------------------
__device__ __forceinline__ uint32_t smem_u32(const void* p) {
    return (uint32_t)__cvta_generic_to_shared(p);
}
__device__ __forceinline__ void ldsm_x4(uint32_t& r0, uint32_t& r1, uint32_t& r2,
                                        uint32_t& r3, uint32_t addr) {
    asm volatile("ldmatrix.sync.aligned.m8n8.x4.shared.b16 {%0,%1,%2,%3},[%4];"
                 : "=r"(r0), "=r"(r1), "=r"(r2), "=r"(r3) : "r"(addr));
}
__device__ __forceinline__ void ldsm_x4t(uint32_t& r0, uint32_t& r1, uint32_t& r2,
                                         uint32_t& r3, uint32_t addr) {
    asm volatile("ldmatrix.sync.aligned.m8n8.x4.trans.shared.b16 {%0,%1,%2,%3},[%4];"
                 : "=r"(r0), "=r"(r1), "=r"(r2), "=r"(r3) : "r"(addr));
}
__device__ __forceinline__ void mma_f16(float c[4], uint32_t a0, uint32_t a1,
                                        uint32_t a2, uint32_t a3,
                                        uint32_t b0, uint32_t b1) {
    asm volatile(
        "mma.sync.aligned.m16n8k16.row.col.f32.f16.f16.f32 "
        "{%0,%1,%2,%3},{%4,%5,%6,%7},{%8,%9},{%0,%1,%2,%3};"
        : "+f"(c[0]), "+f"(c[1]), "+f"(c[2]), "+f"(c[3])
        : "r"(a0), "r"(a1), "r"(a2), "r"(a3), "r"(b0), "r"(b1));
}
__device__ __forceinline__ void st_half4(__half* p, float4 v) {
    __half2 h0 = __floats2half2_rn(v.x, v.y);
    __half2 h1 = __floats2half2_rn(v.z, v.w);
    uint2 u;
    u.x = *(uint32_t*)&h0;
    u.y = *(uint32_t*)&h1;
    *(uint2*)p = u;
}
__device__ __forceinline__ void cp16(uint32_t dst, const void* src) {
    asm volatile("cp.async.ca.shared.global [%0], [%1], 16;" :: "r"(dst), "l"(src));
}
__device__ __forceinline__ void cp_commit() {
    asm volatile("cp.async.commit_group;" ::: "memory");
}
template <int N>
__device__ __forceinline__ void cp_wait() {
    asm volatile("cp.async.wait_group %0;" :: "n"(N) : "memory");
}

// ---------------- fp32 -> fp16 conversion ------------------------------------
__global__ void cvt_f2h(const float* __restrict__ src, __half* __restrict__ dst, int n)
{
    int i = (blockIdx.x * blockDim.x + threadIdx.x) * 4;
    if (i < n) st_half4(dst + i, *(const float4*)(src + i));
}

// ---------------- fp16 cp.async pipelined GEMM -------------------------------
#define TM 128
#define TN 128
#define TK 32
#define AST 40    // halves; 80B row stride -> conflict-free ldmatrix
#define BST 136   // halves; 272B row stride -> conflict-free ldmatrix
#define STG 3
#define ASZ (TM * AST * 2)
#define BSZ (TK * BST * 2)

__global__ __launch_bounds__(256) void h16_gemm(
    const __half* __restrict__ A,
    const __half* __restrict__ B0, float* __restrict__ C0,
    const __half* __restrict__ B1, float* __restrict__ C1,
    int M, int N, int K)
{
    __shared__ __align__(16) __half As[STG][TM][AST];
    __shared__ __align__(16) __half Bs[STG][TK][BST];

    const __half* B = (blockIdx.z == 0) ? B0 : B1;
    float* C        = (blockIdx.z == 0) ? C0 : C1;

    int tid = threadIdx.x, lane = tid & 31, wid = tid >> 5;
    int wm = wid & 3, wn = wid >> 2;
    int g = lane >> 2, tg = lane & 3;

    const __half* Ab = A + (size_t)blockIdx.y * TM * K;
    const __half* Bb = B + (size_t)blockIdx.x * TN;

    float acc[2][8][4];
#pragma unroll
    for (int i = 0; i < 2; i++)
#pragma unroll
        for (int j = 0; j < 8; j++)
#pragma unroll
            for (int r = 0; r < 4; r++) acc[i][j][r] = 0.f;

    int ar0 = tid >> 2, ac0 = (tid & 3) * 8;
    int ar1 = (tid + 256) >> 2, ac1 = ((tid + 256) & 3) * 8;
    int br0 = tid >> 4, bc0 = (tid & 15) * 8;
    int br1 = (tid + 256) >> 4, bc1 = ((tid + 256) & 15) * 8;
    uint32_t aD0 = smem_u32(&As[0][ar0][ac0]);
    uint32_t aD1 = smem_u32(&As[0][ar1][ac1]);
    uint32_t bD0 = smem_u32(&Bs[0][br0][bc0]);
    uint32_t bD1 = smem_u32(&Bs[0][br1][bc1]);

    uint32_t aAddr[2], bAddr[4];
    {
        int arow = wm * 32 + (lane & 15);
        int acol = (lane >> 4) * 8;
        aAddr[0] = smem_u32(&As[0][arow][acol]);
        aAddr[1] = smem_u32(&As[0][arow + 16][acol]);
        int brow = ((lane >> 3) & 1) * 8 + (lane & 7);
        int bcol = wn * 64 + ((lane >> 4) & 1) * 8;
#pragma unroll
        for (int nb = 0; nb < 4; nb++)
            bAddr[nb] = smem_u32(&Bs[0][brow][bcol + nb * 16]);
    }

    int nt = K / TK;

#pragma unroll
    for (int p = 0; p < 2; p++) {
        int k0 = p * TK;
        cp16(aD0 + p * ASZ, Ab + (size_t)ar0 * K + k0 + ac0);
        cp16(aD1 + p * ASZ, Ab + (size_t)ar1 * K + k0 + ac1);
        cp16(bD0 + p * BSZ, Bb + (size_t)(k0 + br0) * N + bc0);
        cp16(bD1 + p * BSZ, Bb + (size_t)(k0 + br1) * N + bc1);
        cp_commit();
    }

    int st = 0;
    for (int t = 0; t < nt; t++) {
        cp_wait<1>();
        __syncthreads();

        uint32_t aOff = (uint32_t)(st * ASZ);
        uint32_t bOff = (uint32_t)(st * BSZ);
#pragma unroll
        for (int ks = 0; ks < 2; ks++) {
            uint32_t af[2][4];
            ldsm_x4(af[0][0], af[0][1], af[0][2], af[0][3], aAddr[0] + aOff + ks * 32);
            ldsm_x4(af[1][0], af[1][1], af[1][2], af[1][3], aAddr[1] + aOff + ks * 32);
            uint32_t bf[8][2];
#pragma unroll
            for (int nb = 0; nb < 4; nb++) {
                uint32_t r0, r1, r2, r3;
                ldsm_x4t(r0, r1, r2, r3, bAddr[nb] + bOff + ks * (16 * BST * 2));
                bf[2 * nb][0] = r0; bf[2 * nb][1] = r1;
                bf[2 * nb + 1][0] = r2; bf[2 * nb + 1][1] = r3;
            }
#pragma unroll
            for (int mf = 0; mf < 2; mf++)
#pragma unroll
                for (int fn = 0; fn < 8; fn++)
                    mma_f16(acc[mf][fn], af[mf][0], af[mf][1], af[mf][2], af[mf][3],
                            bf[fn][0], bf[fn][1]);
        }
        __syncthreads();

        if (t + 2 < nt) {
            int ns = (st + 2) % STG;
            int k0 = (t + 2) * TK;
            cp16(aD0 + ns * ASZ, Ab + (size_t)ar0 * K + k0 + ac0);
            cp16(aD1 + ns * ASZ, Ab + (size_t)ar1 * K + k0 + ac1);
            cp16(bD0 + ns * BSZ, Bb + (size_t)(k0 + br0) * N + bc0);
            cp16(bD1 + ns * BSZ, Bb + (size_t)(k0 + br1) * N + bc1);
        }
        cp_commit();
        st = (st + 1) % STG;
    }

#pragma unroll
    for (int mf = 0; mf < 2; mf++) {
        int row0 = blockIdx.y * TM + wm * 32 + mf * 16 + g;
#pragma unroll
        for (int fn = 0; fn < 8; fn++) {
            int col = blockIdx.x * TN + wn * 64 + fn * 8 + tg * 2;
            *(float2*)&C[(size_t)row0 * N + col]       = make_float2(acc[mf][fn][0], acc[mf][fn][1]);
            *(float2*)&C[(size_t)(row0 + 8) * N + col] = make_float2(acc[mf][fn][2], acc[mf][fn][3]);
        }
    }
}

// ---------------- RoPE on Q -> fp16 (fold 1/sqrt(HD)) -----------------------
__global__ void rope_q_kernel(const float* __restrict__ qf,
                              const float* __restrict__ cosp,
                              const float* __restrict__ sinp,
                              __half* __restrict__ qh)
{
    int idx = blockIdx.x * blockDim.x + threadIdx.x;
    if (idx >= Bsz * SEQ * NH * 32) return;
    int d  = idx & 31;
    int h  = (idx >> 5) & 31;
    int bs = idx >> 10;
    int s  = bs & (SEQ - 1);
    const float* base = qf + ((size_t)bs * NH + h) * HD;
    float x1 = base[d];
    float x2 = base[d + 32];
    float c  = cosp[s * HD + d];
    float sn = sinp[s * HD + d];
    const float scale = 0.125f;
    __half* dst = qh + ((size_t)bs * NH + h) * HD;
    dst[d]      = __float2half_rn((x1 * c - x2 * sn) * scale);
    dst[d + 32] = __float2half_rn((x2 * c + x1 * sn) * scale);
}

// ---------------- RoPE on K + transpose; fp32 (next_k) + fp16 copies --------
__global__ void rope_k_kernel(const float* __restrict__ kraw,
                              const float* __restrict__ cosp,
                              const float* __restrict__ sinp,
                              float* __restrict__ nk,
                              __half* __restrict__ kh)
{
    int idx = blockIdx.x * blockDim.x + threadIdx.x;
    if (idx >= Bsz * SEQ * NKV * 32) return;
    int d  = idx & 31;
    int kv = (idx >> 5) & 7;
    int bs = idx >> 8;
    int s  = bs & (SEQ - 1);
    int b  = bs >> 11;
    const float* src = kraw + (size_t)bs * (NKV * HD) + kv * HD;
    float x1 = src[d];
    float x2 = src[d + 32];
    float c  = cosp[s * HD + d];
    float sn = sinp[s * HD + d];
    float r1 = x1 * c - x2 * sn;
    float r2 = x2 * c + x1 * sn;
    size_t o = (((size_t)b * NKV + kv) * SEQ + s) * HD;
    nk[o + d]      = r1;
    nk[o + d + 32] = r2;
    kh[o + d]      = __float2half_rn(r1);
    kh[o + d + 32] = __float2half_rn(r2);
}

// ---------------- V transpose; fp32 (next_v) + fp16 copies -------------------
__global__ void vtrans_kernel(const float* __restrict__ vraw,
                              float* __restrict__ nv,
                              __half* __restrict__ vh)
{
    int idx = blockIdx.x * blockDim.x + threadIdx.x;
    if (idx >= Bsz * SEQ * NKV * HD) return;
    int d  = idx & 63;
    int kv = (idx >> 6) & 7;
    int bs = idx >> 9;
    int s  = bs & (SEQ - 1);
    int b  = bs >> 11;
    float v = vraw[(size_t)bs * (NKV * HD) + kv * HD + d];
    size_t o = (((size_t)b * NKV + kv) * SEQ + s) * HD + d;
    nv[o] = v;
    vh[o] = __float2half_rn(v);
}

// ---------------- Tensor-core flash attention (causal) -----------------------
// grid (S/128, NH, B), 256 threads (8 warps, 16 q-rows each). All fp16 in.
// cp.async double-buffered 64-key K/V tiles. Output fp16.
#define QTILE 128
#define KTILE 64
#define QST 72
#define KSTGB (KTILE * QST * 2)   // 9216 B per K (or V) stage
#define ATTN_SMEM ((QTILE + 4 * KTILE) * QST * 2)  // 55296 B

__global__ __launch_bounds__(256) void attn_h16(
    const __half* __restrict__ q,    // (B,S,H,D)
    const __half* __restrict__ kk,   // (B,KV,S,D)
    const __half* __restrict__ vv,   // (B,KV,S,D)
    __half* __restrict__ out)        // (B,S,H,D)
{
    extern __shared__ __align__(16) __half sm[];
    __half (*Qh)[QST] = (__half(*)[QST])sm;                          // 128 rows
    __half (*Ks)[QST] = (__half(*)[QST])(sm + QTILE * QST);          // 2 x 64 rows
    __half (*Vs)[QST] = (__half(*)[QST])(sm + (QTILE + 2 * KTILE) * QST);

    int qt = blockIdx.x, h = blockIdx.y, b = blockIdx.z;
    int kv = h >> 2;
    int tid = threadIdx.x, lane = tid & 31, w = tid >> 5;
    int g = lane >> 2, tg = lane & 3;

    const __half* qbase = q + (((size_t)b * SEQ + (size_t)qt * QTILE) * NH + h) * HD;
    const __half* kbase = kk + ((size_t)b * NKV + kv) * SEQ * HD;
    const __half* vbase = vv + ((size_t)b * NKV + kv) * SEQ * HD;

    // K/V cp.async chunk coords (512 16B-chunks per tensor, 2 per thread)
    int kr0 = tid >> 3, kc0 = (tid & 7) * 8;
    int kr1 = (tid + 256) >> 3, kc1 = ((tid + 256) & 7) * 8;
    uint32_t ksD0 = smem_u32(&Ks[kr0][kc0]), ksD1 = smem_u32(&Ks[kr1][kc1]);
    uint32_t vsD0 = smem_u32(&Vs[kr0][kc0]), vsD1 = smem_u32(&Vs[kr1][kc1]);

    int nk = 2 * qt + 2;

    // group 0: Q tile (1024 chunks, 4/thread) + K/V tile 0
#pragma unroll
    for (int i = 0; i < 4; i++) {
        int c = tid + i * 256;
        int r = c >> 3, col = (c & 7) * 8;
        cp16(smem_u32(&Qh[r][col]), qbase + (size_t)r * NH * HD + col);
    }
    {
        const __half* kp = kbase;
        const __half* vp = vbase;
        cp16(ksD0, kp + (size_t)kr0 * HD + kc0);
        cp16(ksD1, kp + (size_t)kr1 * HD + kc1);
        cp16(vsD0, vp + (size_t)kr0 * HD + kc0);
        cp16(vsD1, vp + (size_t)kr1 * HD + kc1);
    }
    cp_commit();
    // group 1: K/V tile 1 (nk >= 2 always)
    {
        const __half* kp = kbase + (size_t)KTILE * HD;
        const __half* vp = vbase + (size_t)KTILE * HD;
        cp16(ksD0 + KSTGB, kp + (size_t)kr0 * HD + kc0);
        cp16(ksD1 + KSTGB, kp + (size_t)kr1 * HD + kc1);
        cp16(vsD0 + KSTGB, vp + (size_t)kr0 * HD + kc0);
        cp16(vsD1 + KSTGB, vp + (size_t)kr1 * HD + kc1);
    }
    cp_commit();

    // ldmatrix lane addresses (stage 0)
    uint32_t kAddr[4], vAddr[4], qAddr;
    {
        int krow = (lane & 15), kcol = (lane >> 4) * 8;
#pragma unroll
        for (int nb = 0; nb < 4; nb++)
            kAddr[nb] = smem_u32(&Ks[nb * 16 + krow][kcol]);
        int vrow = ((lane >> 3) & 1) * 8 + (lane & 7);
        int vcol = ((lane >> 4) & 1) * 8;
#pragma unroll
        for (int nb = 0; nb < 4; nb++)
            vAddr[nb] = smem_u32(&Vs[vrow][vcol + nb * 16]);
        int arow = w * 16 + (lane & 15), acol = (lane >> 4) * 8;
        qAddr = smem_u32(&Qh[arow][acol]);
    }

    uint32_t aqh[4][4];
    float oacc[8][4];
#pragma unroll
    for (int fn = 0; fn < 8; fn++)
#pragma unroll
        for (int r = 0; r < 4; r++) oacc[fn][r] = 0.f;
    float m0 = -1e30f, m1 = -1e30f, l0 = 0.f, l1 = 0.f;

    int r0loc = w * 16 + g;
    int rg0 = qt * QTILE + r0loc;
    int rg1 = rg0 + 8;

    for (int kt = 0; kt < nk; kt++) {
        cp_wait<1>();
        __syncthreads();

        if (kt == 0) {
#pragma unroll
            for (int ks = 0; ks < 4; ks++)
                ldsm_x4(aqh[ks][0], aqh[ks][1], aqh[ks][2], aqh[ks][3], qAddr + ks * 32);
        }

        uint32_t so = (uint32_t)((kt & 1) * KSTGB);

        // scores S = Q @ K^T (128x64 per block, 16x64 per warp)
        float s[8][4];
#pragma unroll
        for (int fn = 0; fn < 8; fn++)
#pragma unroll
            for (int r = 0; r < 4; r++) s[fn][r] = 0.f;

#pragma unroll
        for (int ks = 0; ks < 4; ks++) {
            uint32_t kb[8][2];
#pragma unroll
            for (int nb = 0; nb < 4; nb++) {
                uint32_t r0, r1, r2, r3;
                ldsm_x4(r0, r1, r2, r3, kAddr[nb] + so + ks * 32);
                kb[2 * nb][0] = r0; kb[2 * nb + 1][0] = r1;
                kb[2 * nb][1] = r2; kb[2 * nb + 1][1] = r3;
            }
#pragma unroll
            for (int fn = 0; fn < 8; fn++)
                mma_f16(s[fn], aqh[ks][0], aqh[ks][1], aqh[ks][2], aqh[ks][3],
                        kb[fn][0], kb[fn][1]);
        }

        // causal mask (only the last two k-tiles can cross the diagonal)
        if (kt >= 2 * qt) {
            int cb = kt * KTILE;
#pragma unroll
            for (int fn = 0; fn < 8; fn++) {
                int c = cb + fn * 8 + 2 * tg;
                if (c > rg0)     s[fn][0] = -1e30f;
                if (c + 1 > rg0) s[fn][1] = -1e30f;
                if (c > rg1)     s[fn][2] = -1e30f;
                if (c + 1 > rg1) s[fn][3] = -1e30f;
            }
        }

        // online softmax
        float mx0 = -1e30f, mx1 = -1e30f;
#pragma unroll
        for (int fn = 0; fn < 8; fn++) {
            mx0 = fmaxf(mx0, fmaxf(s[fn][0], s[fn][1]));
            mx1 = fmaxf(mx1, fmaxf(s[fn][2], s[fn][3]));
        }
        mx0 = fmaxf(mx0, __shfl_xor_sync(0xffffffffu, mx0, 1));
        mx0 = fmaxf(mx0, __shfl_xor_sync(0xffffffffu, mx0, 2));
        mx1 = fmaxf(mx1, __shfl_xor_sync(0xffffffffu, mx1, 1));
        mx1 = fmaxf(mx1, __shfl_xor_sync(0xffffffffu, mx1, 2));
        float mn0 = fmaxf(m0, mx0), mn1 = fmaxf(m1, mx1);
        float c0 = __expf(m0 - mn0), c1 = __expf(m1 - mn1);
        m0 = mn0; m1 = mn1;

        float su0 = 0.f, su1 = 0.f;
        uint32_t pA[4][4];
#pragma unroll
        for (int fn = 0; fn < 8; fn++) {
            float e0 = __expf(s[fn][0] - mn0);
            float e1 = __expf(s[fn][1] - mn0);
            float e2 = __expf(s[fn][2] - mn1);
            float e3 = __expf(s[fn][3] - mn1);
            su0 += e0 + e1;
            su1 += e2 + e3;
            __half2 p01 = __floats2half2_rn(e0, e1);
            __half2 p23 = __floats2half2_rn(e2, e3);
            int kq = fn >> 1;
            int hi = (fn & 1) * 2;
            pA[kq][hi]     = *(uint32_t*)&p01;
            pA[kq][hi + 1] = *(uint32_t*)&p23;
        }
        su0 += __shfl_xor_sync(0xffffffffu, su0, 1);
        su0 += __shfl_xor_sync(0xffffffffu, su0, 2);
        su1 += __shfl_xor_sync(0xffffffffu, su1, 1);
        su1 += __shfl_xor_sync(0xffffffffu, su1, 2);
        l0 = l0 * c0 + su0;
        l1 = l1 * c1 + su1;

#pragma unroll
        for (int fn = 0; fn < 8; fn++) {
            oacc[fn][0] *= c0; oacc[fn][1] *= c0;
            oacc[fn][2] *= c1; oacc[fn][3] *= c1;
        }

        // O += P @ V
#pragma unroll
        for (int kq = 0; kq < 4; kq++) {
            uint32_t vb[8][2];
#pragma unroll
            for (int nb = 0; nb < 4; nb++) {
                uint32_t r0, r1, r2, r3;
                ldsm_x4t(r0, r1, r2, r3, vAddr[nb] + so + kq * (16 * QST * 2));
                vb[2 * nb][0] = r0; vb[2 * nb][1] = r1;
                vb[2 * nb + 1][0] = r2; vb[2 * nb + 1][1] = r3;
            }
#pragma unroll
            for (int fn = 0; fn < 8; fn++)
                mma_f16(oacc[fn], pA[kq][0], pA[kq][1], pA[kq][2], pA[kq][3],
                        vb[fn][0], vb[fn][1]);
        }

        __syncthreads();
        if (kt + 2 < nk) {
            const __half* kp = kbase + (size_t)(kt + 2) * KTILE * HD;
            const __half* vp = vbase + (size_t)(kt + 2) * KTILE * HD;
            uint32_t ds = (uint32_t)((kt & 1) * KSTGB);
            cp16(ksD0 + ds, kp + (size_t)kr0 * HD + kc0);
            cp16(ksD1 + ds, kp + (size_t)kr1 * HD + kc1);
            cp16(vsD0 + ds, vp + (size_t)kr0 * HD + kc0);
            cp16(vsD1 + ds, vp + (size_t)kr1 * HD + kc1);
        }
        cp_commit();
    }

    // epilogue (fp16 out)
    float inv0 = 1.f / l0, inv1 = 1.f / l1;
    __half* ob = out + (((size_t)b * SEQ + rg0) * NH + h) * HD;
#pragma unroll
    for (int fn = 0; fn < 8; fn++) {
        int c = fn * 8 + 2 * tg;
        __half2 lo = __floats2half2_rn(oacc[fn][0] * inv0, oacc[fn][1] * inv0);
        __half2 hi = __floats2half2_rn(oacc[fn][2] * inv1, oacc[fn][3] * inv1);
        *(__half2*)(ob + c) = lo;
        *(__half2*)(ob + (size_t)8 * NH * HD + c) = hi;
    }
}

// ---------------- launch -----------------------------------------------------
extern "C" void kernel_launch(void* const* d_in, const int* in_sizes, int n_in,
                              void* d_out, int out_size)
{
    const float* x    = (const float*)d_in[0];
    // d_in[1] = mask (causal) — analytic
    const float* cosp = (const float*)d_in[2];
    const float* sinp = (const float*)d_in[3];
    const float* Wq   = (const float*)d_in[4];
    const float* Wk   = (const float*)d_in[5];
    const float* Wv   = (const float*)d_in[6];
    const float* Wo   = (const float*)d_in[7];

    float* out    = (float*)d_out;
    float* next_k = out + (size_t)Bsz * SEQ * EMB;
    float* next_v = next_k + (size_t)Bsz * NKV * SEQ * HD;

    float *qbuf, *kbuf, *vbuf;
    __half *xh, *wqh, *wkh, *wvh, *woh, *qh, *kh, *vh, *ah;
    cudaGetSymbolAddress((void**)&qbuf, g_q);
    cudaGetSymbolAddress((void**)&kbuf, g_k);
    cudaGetSymbolAddress((void**)&vbuf, g_v);
    cudaGetSymbolAddress((void**)&xh,  g_xh);
    cudaGetSymbolAddress((void**)&wqh, g_wqh);
    cudaGetSymbolAddress((void**)&wkh, g_wkh);
    cudaGetSymbolAddress((void**)&wvh, g_wvh);
    cudaGetSymbolAddress((void**)&woh, g_woh);
    cudaGetSymbolAddress((void**)&qh,  g_qh);
    cudaGetSymbolAddress((void**)&kh,  g_kh);
    cudaGetSymbolAddress((void**)&vh,  g_vh);
    cudaGetSymbolAddress((void**)&ah,  g_ah);

    static bool attn_cfg = false;
    if (!attn_cfg) {
        cudaFuncSetAttribute(attn_h16, cudaFuncAttributeMaxDynamicSharedMemorySize,
                             ATTN_SMEM);
        attn_cfg = true;
    }

    // fp32 -> fp16 conversions
    cvt_f2h<<<(BSxS * EMB) / 1024, 256>>>(x, xh, BSxS * EMB);
    cvt_f2h<<<(EMB * EMB) / 1024, 256>>>(Wq, wqh, EMB * EMB);
    cvt_f2h<<<(EMB * NKV * HD) / 1024, 256>>>(Wk, wkh, EMB * NKV * HD);
    cvt_f2h<<<(EMB * NKV * HD) / 1024, 256>>>(Wv, wvh, EMB * NKV * HD);
    cvt_f2h<<<(EMB * EMB) / 1024, 256>>>(Wo, woh, EMB * EMB);

    // Projections
    h16_gemm<<<dim3(EMB / TN, BSxS / TM, 1), 256>>>(xh, wqh, qbuf, wqh, qbuf,
                                                    BSxS, EMB, EMB);
    h16_gemm<<<dim3((NKV * HD) / TN, BSxS / TM, 2), 256>>>(xh, wkh, kbuf, wvh, vbuf,
                                                           BSxS, NKV * HD, EMB);

    // RoPE + layout (fp32 outputs to d_out, fp16 copies for attention)
    rope_q_kernel<<<(Bsz * SEQ * NH * 32) / 256, 256>>>(qbuf, cosp, sinp, qh);
    rope_k_kernel<<<(Bsz * SEQ * NKV * 32) / 256, 256>>>(kbuf, cosp, sinp, next_k, kh);
    vtrans_kernel<<<(Bsz * SEQ * NKV * HD) / 256, 256>>>(vbuf, next_v, vh);

    // Flash attention (fp16 in/out, cp.async double-buffered)
    attn_h16<<<dim3(SEQ / QTILE, NH, Bsz), 256, ATTN_SMEM>>>(qh, kh, vh, ah);

    // Output projection
    h16_gemm<<<dim3(EMB / TN, BSxS / TM, 1), 256>>>(ah, woh, out, woh, out,
                                                    BSxS, EMB, EMB);
}